// round 1
// baseline (speedup 1.0000x reference)
#include <cuda_runtime.h>
#include <cuda_bf16.h>
#include <cstddef>

#define NN 8
#define CC 256
#define HH 64
#define WW 64
#define LL (HH*WW)      // 4096
#define GG 8
#define KK 9
#define OMC (GG*KK*3)   // 216

// Scratch (allocation-free: __device__ globals)
__device__ float g_value[(size_t)NN*LL*CC];   // (n, L, C)
__device__ float g_omin [(size_t)NN*CC*LL];   // (n, C, L)  depthwise output
__device__ float g_om   [(size_t)NN*LL*OMC];  // (n, L, 216)
__device__ float g_samp [(size_t)NN*LL*CC];   // (n, L, C)

// ---------------------------------------------------------------------------
// Generic batched GEMM: out[m][j] = sum_k a(m,k) * W[j*Kc+k] (+ bias[j])
//   A_COL  : a(m,k) = A[k*M + m]   (NCHW-style, channel-major)
//   !A_COL : a(m,k) = A[m*Kc + k]  (row-major)
//   OUT_T  : out[j*M + m]  else out[m*Nj + j]
// Batch via blockIdx.z; A stride M*Kc, out stride M*Nj.
// BM=BN=128, BK=16, 256 threads, 8x8 microtile.
// ---------------------------------------------------------------------------
template<bool A_COL, bool OUT_T, bool HAS_BIAS>
__global__ void __launch_bounds__(256)
gemm_k(const float* __restrict__ A, const float* __restrict__ Wt,
       const float* __restrict__ bias, float* __restrict__ out,
       int M, int Nj, int Kc)
{
    const int BM = 128, BN = 128, BK = 16;
    __shared__ float As[BK][BM];
    __shared__ float Bs[BK][BN];

    const int bz = blockIdx.z;
    A   += (size_t)bz * M * Kc;
    out += (size_t)bz * M * Nj;

    const int m0 = blockIdx.y * BM;
    const int j0 = blockIdx.x * BN;
    const int tid = threadIdx.x;
    const int tx = tid & 15;        // j direction (16)
    const int ty = tid >> 4;        // m direction (16)

    float acc[8][8];
    #pragma unroll
    for (int i = 0; i < 8; i++)
        #pragma unroll
        for (int j = 0; j < 8; j++) acc[i][j] = 0.f;

    for (int k0 = 0; k0 < Kc; k0 += BK) {
        // ---- load A tile (128 x 16) ----
        if (A_COL) {
            #pragma unroll
            for (int p = 0; p < 2; p++) {
                int lin = (tid + p * 256) * 4;       // 0..2044
                int m = lin & 127;
                int k = lin >> 7;
                float4 v = *(const float4*)(A + (size_t)(k0 + k) * M + m0 + m);
                *(float4*)&As[k][m] = v;
            }
        } else {
            #pragma unroll
            for (int p = 0; p < 2; p++) {
                int lin = (tid + p * 256) * 4;
                int k = lin & 15;                    // 0,4,8,12
                int m = lin >> 4;                    // 0..127
                float4 v = *(const float4*)(A + (size_t)(m0 + m) * Kc + k0 + k);
                As[k + 0][m] = v.x; As[k + 1][m] = v.y;
                As[k + 2][m] = v.z; As[k + 3][m] = v.w;
            }
        }
        // ---- load W tile (128 x 16), row-guarded for Nj=216 ----
        #pragma unroll
        for (int p = 0; p < 2; p++) {
            int lin = (tid + p * 256) * 4;
            int k = lin & 15;
            int j = lin >> 4;
            float4 v = make_float4(0.f, 0.f, 0.f, 0.f);
            if (j0 + j < Nj)
                v = *(const float4*)(Wt + (size_t)(j0 + j) * Kc + k0 + k);
            Bs[k + 0][j] = v.x; Bs[k + 1][j] = v.y;
            Bs[k + 2][j] = v.z; Bs[k + 3][j] = v.w;
        }
        __syncthreads();

        #pragma unroll
        for (int kk = 0; kk < BK; kk++) {
            float a[8], b[8];
            #pragma unroll
            for (int i = 0; i < 8; i++) a[i] = As[kk][ty * 8 + i];
            #pragma unroll
            for (int j = 0; j < 8; j++) b[j] = Bs[kk][tx * 8 + j];
            #pragma unroll
            for (int i = 0; i < 8; i++)
                #pragma unroll
                for (int j = 0; j < 8; j++)
                    acc[i][j] += a[i] * b[j];
        }
        __syncthreads();
    }

    // ---- epilogue ----
    #pragma unroll
    for (int i = 0; i < 8; i++) {
        int m = m0 + ty * 8 + i;
        #pragma unroll
        for (int j = 0; j < 8; j++) {
            int jj = j0 + tx * 8 + j;
            if (jj < Nj) {
                float v = acc[i][j];
                if (HAS_BIAS) v += bias[jj];
                if (OUT_T) out[(size_t)jj * M + m] = v;
                else       out[(size_t)m * Nj + jj] = v;
            }
        }
    }
}

// ---------------------------------------------------------------------------
// Depthwise 3x3 conv, SAME zero padding. x:(N,C,H,W) -> out:(N,C,L)
// ---------------------------------------------------------------------------
__global__ void __launch_bounds__(256)
dw_k(const float* __restrict__ x, const float* __restrict__ w,
     const float* __restrict__ b, float* __restrict__ out)
{
    int idx = blockIdx.x * blockDim.x + threadIdx.x;
    if (idx >= NN * CC * LL) return;
    int xx = idx & (WW - 1);
    int yy = (idx >> 6) & (HH - 1);
    int c  = (idx >> 12) & (CC - 1);

    float s = b[c];
    const float* wc = w + c * 9;
    #pragma unroll
    for (int dy = -1; dy <= 1; dy++) {
        int ny = yy + dy;
        if (ny < 0 || ny >= HH) continue;
        #pragma unroll
        for (int dx = -1; dx <= 1; dx++) {
            int nx = xx + dx;
            if (nx < 0 || nx >= WW) continue;
            s += x[idx + dy * WW + dx] * wc[(dy + 1) * 3 + (dx + 1)];
        }
    }
    out[idx] = s;
}

// ---------------------------------------------------------------------------
// Deformable bilinear sampling. One warp per (n, l, g); lane = channel in cg=32.
// value:(n,L,C), om:(n,L,216) -> sampled:(n,L,C)
// sampled[n,l,g*32+lane] = sum_k mask[g,k] * bilinear(value[n, p_k, g*32+lane])
// ---------------------------------------------------------------------------
__global__ void __launch_bounds__(256)
samp_k(const float* __restrict__ value, const float* __restrict__ om,
       float* __restrict__ sampled)
{
    int t = blockIdx.x * blockDim.x + threadIdx.x;
    int lane = t & 31;
    int wid = t >> 5;               // (n*L + l)*G + g
    if (wid >= NN * LL * GG) return;
    int g  = wid & (GG - 1);
    int nl = wid >> 3;              // n*L + l
    int l  = nl & (LL - 1);
    int n  = nl >> 12;
    int yy = l >> 6, xx = l & 63;

    const float* omp = om + (size_t)nl * OMC + g * 27;
    const float* vb  = value + (size_t)n * LL * CC + g * 32 + lane;

    float acc = 0.f;
    #pragma unroll
    for (int k = 0; k < KK; k++) {
        float offy = omp[2 * k];
        float offx = omp[2 * k + 1];
        float msk  = omp[18 + k];
        float py = (float)(yy + k / 3 - 1) + offy;
        float px = (float)(xx + k % 3 - 1) + offx;
        float fy = floorf(py), fx = floorf(px);
        float tyf = py - fy, txf = px - fx;
        int y0 = (int)fy, x0 = (int)fx;

        bool yv0 = (y0 >= 0) && (y0 < HH);
        bool yv1 = (y0 + 1 >= 0) && (y0 + 1 < HH);
        bool xv0 = (x0 >= 0) && (x0 < WW);
        bool xv1 = (x0 + 1 >= 0) && (x0 + 1 < WW);

        float v00 = 0.f, v01 = 0.f, v10 = 0.f, v11 = 0.f;
        if (yv0 && xv0) v00 = vb[(size_t)(y0 * WW + x0) * CC];
        if (yv0 && xv1) v01 = vb[(size_t)(y0 * WW + x0 + 1) * CC];
        if (yv1 && xv0) v10 = vb[(size_t)((y0 + 1) * WW + x0) * CC];
        if (yv1 && xv1) v11 = vb[(size_t)((y0 + 1) * WW + x0 + 1) * CC];

        float bi = (1.f - tyf) * ((1.f - txf) * v00 + txf * v01)
                 +        tyf  * ((1.f - txf) * v10 + txf * v11);
        acc += msk * bi;
    }
    sampled[(size_t)nl * CC + g * 32 + lane] = acc;
}

// ---------------------------------------------------------------------------
extern "C" void kernel_launch(void* const* d_in, const int* in_sizes, int n_in,
                              void* d_out, int out_size)
{
    const float* x   = (const float*)d_in[0];
    const float* dww = (const float*)d_in[1];
    const float* dwb = (const float*)d_in[2];
    const float* omw = (const float*)d_in[3];
    const float* omb = (const float*)d_in[4];
    const float* vpw = (const float*)d_in[5];
    const float* vpb = (const float*)d_in[6];
    const float* opw = (const float*)d_in[7];
    float* out = (float*)d_out;

    float *pval, *pomin, *pom, *psamp;
    cudaGetSymbolAddress((void**)&pval,  g_value);
    cudaGetSymbolAddress((void**)&pomin, g_omin);
    cudaGetSymbolAddress((void**)&pom,   g_om);
    cudaGetSymbolAddress((void**)&psamp, g_samp);

    // 1) value projection: (n,C,L) x -> value (n,L,C)
    gemm_k<true, false, true><<<dim3(CC / 128, LL / 128, NN), 256>>>(
        x, vpw, vpb, pval, LL, CC, CC);

    // 2) depthwise conv -> om_in (n,C,L)
    dw_k<<<(NN * CC * LL + 255) / 256, 256>>>(x, dww, dwb, pomin);

    // 3) offset/mask projection: om_in -> om (n,L,216)
    gemm_k<true, false, true><<<dim3((OMC + 127) / 128, LL / 128, NN), 256>>>(
        pomin, omw, omb, pom, LL, OMC, CC);

    // 4) deformable sampling -> sampled (n,L,C)
    samp_k<<<(NN * LL * GG * 32 + 255) / 256, 256>>>(pval, pom, psamp);

    // 5) output projection, write transposed directly to d_out (n,C,H,W)
    gemm_k<false, true, false><<<dim3(CC / 128, LL / 128, NN), 256>>>(
        psamp, opw, nullptr, out, LL, CC, CC);
}

// round 2
// speedup vs baseline: 1.8654x; 1.8654x over previous
#include <cuda_runtime.h>
#include <cuda_bf16.h>
#include <cstdint>
#include <cstddef>

#define NN 8
#define CC 256
#define HH 64
#define WW 64
#define LL (HH*WW)      // 4096
#define GG 8
#define KK 9
#define OMC (GG*KK*3)   // 216

// Scratch (allocation-free: __device__ globals)
__device__ float g_value[(size_t)NN*LL*CC];   // (n, L, C)
__device__ float g_omin [(size_t)NN*CC*LL];   // (n, C, L)  depthwise output
__device__ float g_om   [(size_t)NN*LL*OMC];  // (n, L, 216)
__device__ float g_samp [(size_t)NN*LL*CC];   // (n, L, C)

// ---------------------------------------------------------------------------
// tf32 helpers
// ---------------------------------------------------------------------------
__device__ __forceinline__ uint32_t f2tf(float f) {
    uint32_t r; asm("cvt.rna.tf32.f32 %0, %1;" : "=r"(r) : "f"(f)); return r;
}
__device__ __forceinline__ void ldsm4(uint32_t addr, uint32_t& r0, uint32_t& r1,
                                      uint32_t& r2, uint32_t& r3) {
    asm volatile("ldmatrix.sync.aligned.m8n8.x4.shared.b16 {%0,%1,%2,%3}, [%4];"
                 : "=r"(r0), "=r"(r1), "=r"(r2), "=r"(r3) : "r"(addr));
}
__device__ __forceinline__ void mma8(float* d, const uint32_t* a, const uint32_t* b) {
    asm volatile("mma.sync.aligned.m16n8k8.row.col.f32.tf32.tf32.f32 "
                 "{%0,%1,%2,%3}, {%4,%5,%6,%7}, {%8,%9}, {%0,%1,%2,%3};"
                 : "+f"(d[0]), "+f"(d[1]), "+f"(d[2]), "+f"(d[3])
                 : "r"(a[0]), "r"(a[1]), "r"(a[2]), "r"(a[3]),
                   "r"(b[0]), "r"(b[1]));
}

// ---------------------------------------------------------------------------
// tf32 tensor-core batched GEMM: out[m][j] = sum_k a(m,k) * Wt[j*Kc+k] (+bias)
//   A_COL : a(m,k) = A[k*M + m]   else a(m,k) = A[m*Kc + k]
//   OUT_T : out[j*M + m]          else out[m*Nj + j]
// BM=BN=128, BK=16, 256 threads (8 warps, 2x4 warp grid, 64x32 warp tile).
// smem tiles stored fragment-row-major: As[m][k], Bs[j][k], stride 20 words
// (16B-aligned rows, conflict-free ldmatrix).
// ---------------------------------------------------------------------------
template<bool A_COL, bool OUT_T, bool HAS_BIAS>
__global__ void __launch_bounds__(256)
gemm_tc(const float* __restrict__ A, const float* __restrict__ Wt,
        const float* __restrict__ bias, float* __restrict__ out,
        int M, int Nj, int Kc)
{
    constexpr int BM = 128, BN = 128, BK = 16, PAD = 20;
    __shared__ uint32_t As[2][BM][PAD];
    __shared__ uint32_t Bs[2][BN][PAD];

    const int tid = threadIdx.x;
    const int bz = blockIdx.z;
    A   += (size_t)bz * M * Kc;
    out += (size_t)bz * M * Nj;
    const int m0 = blockIdx.y * BM;
    const int j0 = blockIdx.x * BN;

    // ---- staging address setup (2 float4 per thread per operand) ----
    int a_m[2], a_k[2];
    const float* a_ptr[2];
    int b_j[2], b_k[2];
    const float* b_ptr[2];
    bool b_ok[2];
    #pragma unroll
    for (int p = 0; p < 2; p++) {
        int lin = (tid + p * 256) * 4;
        if (A_COL) {
            a_m[p] = lin & 127; a_k[p] = lin >> 7;
            a_ptr[p] = A + (size_t)a_k[p] * M + m0 + a_m[p];
        } else {
            a_k[p] = lin & 15;  a_m[p] = lin >> 4;
            a_ptr[p] = A + (size_t)(m0 + a_m[p]) * Kc + a_k[p];
        }
        b_k[p] = lin & 15; b_j[p] = lin >> 4;
        b_ok[p] = (j0 + b_j[p]) < Nj;
        b_ptr[p] = Wt + (size_t)(j0 + b_j[p]) * Kc + b_k[p];
    }

    // ---- compute-side lane addresses ----
    const int lane = tid & 31, wrp = tid >> 5;
    const int wm = wrp & 1, wn = wrp >> 1;
    const uint32_t as_base = (uint32_t)__cvta_generic_to_shared(&As[0][0][0]);
    const uint32_t bs_base = (uint32_t)__cvta_generic_to_shared(&Bs[0][0][0]);
    const uint32_t BUFB = BM * PAD * 4;   // bytes per buffer (10240)

    const int arow = wm * 64 + (lane & 15);
    const int acol = 4 * (lane >> 4);
    const uint32_t aaddr0 = as_base + (uint32_t)(arow * PAD + acol) * 4;
    const int brow = wn * 32 + (lane & 7) + 8 * (lane >> 4);
    const int bcol = 4 * ((lane >> 3) & 1);
    const uint32_t baddr0 = bs_base + (uint32_t)(brow * PAD + bcol) * 4;

    float acc[4][4][4];
    #pragma unroll
    for (int mi = 0; mi < 4; mi++)
        #pragma unroll
        for (int nj = 0; nj < 4; nj++)
            #pragma unroll
            for (int q = 0; q < 4; q++) acc[mi][nj][q] = 0.f;

    const int KT = Kc / BK;
    float4 ra[2], rb[2];

    // ---- prologue: stage tile 0 into buffer 0 ----
    #pragma unroll
    for (int p = 0; p < 2; p++) {
        ra[p] = *(const float4*)(a_ptr[p]);
        rb[p] = b_ok[p] ? *(const float4*)(b_ptr[p])
                        : make_float4(0.f, 0.f, 0.f, 0.f);
    }
    #pragma unroll
    for (int p = 0; p < 2; p++) {
        if (A_COL) {
            As[0][a_m[p] + 0][a_k[p]] = f2tf(ra[p].x);
            As[0][a_m[p] + 1][a_k[p]] = f2tf(ra[p].y);
            As[0][a_m[p] + 2][a_k[p]] = f2tf(ra[p].z);
            As[0][a_m[p] + 3][a_k[p]] = f2tf(ra[p].w);
        } else {
            uint4 v = make_uint4(f2tf(ra[p].x), f2tf(ra[p].y), f2tf(ra[p].z), f2tf(ra[p].w));
            *(uint4*)&As[0][a_m[p]][a_k[p]] = v;
        }
        uint4 w = make_uint4(f2tf(rb[p].x), f2tf(rb[p].y), f2tf(rb[p].z), f2tf(rb[p].w));
        *(uint4*)&Bs[0][b_j[p]][b_k[p]] = w;
    }
    __syncthreads();

    int buf = 0;
    for (int kt = 0; kt < KT; kt++) {
        // prefetch next tile into registers (overlaps with MMA below)
        if (kt + 1 < KT) {
            #pragma unroll
            for (int p = 0; p < 2; p++) {
                if (A_COL)
                    ra[p] = *(const float4*)(a_ptr[p] + (size_t)(kt + 1) * BK * M);
                else
                    ra[p] = *(const float4*)(a_ptr[p] + (kt + 1) * BK);
                rb[p] = b_ok[p] ? *(const float4*)(b_ptr[p] + (kt + 1) * BK)
                                : make_float4(0.f, 0.f, 0.f, 0.f);
            }
        }

        // compute on current buffer
        const uint32_t abase = aaddr0 + buf * BUFB;
        const uint32_t bbase = baddr0 + buf * BUFB;
        #pragma unroll
        for (int kk = 0; kk < 2; kk++) {
            uint32_t a[4][4], b[4][2];
            #pragma unroll
            for (int mi = 0; mi < 4; mi++)
                ldsm4(abase + (uint32_t)(mi * 16 * PAD + kk * 8) * 4,
                      a[mi][0], a[mi][1], a[mi][2], a[mi][3]);
            #pragma unroll
            for (int njp = 0; njp < 2; njp++)
                ldsm4(bbase + (uint32_t)(njp * 16 * PAD + kk * 8) * 4,
                      b[2 * njp][0], b[2 * njp][1], b[2 * njp + 1][0], b[2 * njp + 1][1]);
            #pragma unroll
            for (int mi = 0; mi < 4; mi++)
                #pragma unroll
                for (int nj = 0; nj < 4; nj++)
                    mma8(acc[mi][nj], a[mi], b[nj]);
        }

        // store prefetched tile into other buffer
        if (kt + 1 < KT) {
            int nb = buf ^ 1;
            #pragma unroll
            for (int p = 0; p < 2; p++) {
                if (A_COL) {
                    As[nb][a_m[p] + 0][a_k[p]] = f2tf(ra[p].x);
                    As[nb][a_m[p] + 1][a_k[p]] = f2tf(ra[p].y);
                    As[nb][a_m[p] + 2][a_k[p]] = f2tf(ra[p].z);
                    As[nb][a_m[p] + 3][a_k[p]] = f2tf(ra[p].w);
                } else {
                    uint4 v = make_uint4(f2tf(ra[p].x), f2tf(ra[p].y), f2tf(ra[p].z), f2tf(ra[p].w));
                    *(uint4*)&As[nb][a_m[p]][a_k[p]] = v;
                }
                uint4 w = make_uint4(f2tf(rb[p].x), f2tf(rb[p].y), f2tf(rb[p].z), f2tf(rb[p].w));
                *(uint4*)&Bs[nb][b_j[p]][b_k[p]] = w;
            }
        }
        __syncthreads();
        buf ^= 1;
    }

    // ---- epilogue ----
    const int r = lane >> 2, c = lane & 3;
    #pragma unroll
    for (int mi = 0; mi < 4; mi++) {
        int m = m0 + wm * 64 + mi * 16 + r;
        #pragma unroll
        for (int nj = 0; nj < 4; nj++) {
            int j = j0 + wn * 32 + nj * 8 + 2 * c;
            if (j < Nj) {
                float bj0 = HAS_BIAS ? bias[j]     : 0.f;
                float bj1 = HAS_BIAS ? bias[j + 1] : 0.f;
                float v0 = acc[mi][nj][0] + bj0;
                float v1 = acc[mi][nj][1] + bj1;
                float v2 = acc[mi][nj][2] + bj0;
                float v3 = acc[mi][nj][3] + bj1;
                if (OUT_T) {
                    out[(size_t)j * M + m]           = v0;
                    out[(size_t)(j + 1) * M + m]     = v1;
                    out[(size_t)j * M + m + 8]       = v2;
                    out[(size_t)(j + 1) * M + m + 8] = v3;
                } else {
                    *(float2*)&out[(size_t)m * Nj + j]       = make_float2(v0, v1);
                    *(float2*)&out[(size_t)(m + 8) * Nj + j] = make_float2(v2, v3);
                }
            }
        }
    }
}

// ---------------------------------------------------------------------------
// Depthwise 3x3 conv, SAME zero padding. x:(N,C,H,W) -> out:(N,C,L)
// ---------------------------------------------------------------------------
__global__ void __launch_bounds__(256)
dw_k(const float* __restrict__ x, const float* __restrict__ w,
     const float* __restrict__ b, float* __restrict__ out)
{
    int idx = blockIdx.x * blockDim.x + threadIdx.x;
    if (idx >= NN * CC * LL) return;
    int xx = idx & (WW - 1);
    int yy = (idx >> 6) & (HH - 1);
    int c  = (idx >> 12) & (CC - 1);

    float s = b[c];
    const float* wc = w + c * 9;
    #pragma unroll
    for (int dy = -1; dy <= 1; dy++) {
        int ny = yy + dy;
        if (ny < 0 || ny >= HH) continue;
        #pragma unroll
        for (int dx = -1; dx <= 1; dx++) {
            int nx = xx + dx;
            if (nx < 0 || nx >= WW) continue;
            s += x[idx + dy * WW + dx] * wc[(dy + 1) * 3 + (dx + 1)];
        }
    }
    out[idx] = s;
}

// ---------------------------------------------------------------------------
// Deformable bilinear sampling. One warp per (n, l, g); lane = channel in cg=32.
// Int32 indexing, shared base pointer per k-point (corner loads are base +
// constant immediate offsets).
// ---------------------------------------------------------------------------
__global__ void __launch_bounds__(256)
samp_k(const float* __restrict__ value, const float* __restrict__ om,
       float* __restrict__ sampled)
{
    int t = blockIdx.x * blockDim.x + threadIdx.x;
    int lane = t & 31;
    int wid = t >> 5;               // (n*L + l)*G + g
    if (wid >= NN * LL * GG) return;
    int g  = wid & (GG - 1);
    int nl = wid >> 3;              // n*L + l
    int l  = nl & (LL - 1);
    int n  = nl >> 12;
    int yy = l >> 6, xx = l & 63;

    const float* omp = om + nl * OMC + g * 27;
    const float* vb  = value + n * (LL * CC) + g * 32 + lane;

    float acc = 0.f;
    #pragma unroll
    for (int k = 0; k < KK; k++) {
        float offy = omp[2 * k];
        float offx = omp[2 * k + 1];
        float msk  = omp[18 + k];
        float py = (float)(yy + k / 3 - 1) + offy;
        float px = (float)(xx + k % 3 - 1) + offx;
        float fy = floorf(py), fx = floorf(px);
        float tyf = py - fy, txf = px - fx;
        int y0 = (int)fy, x0 = (int)fx;

        bool yv0 = (unsigned)y0 < HH;
        bool yv1 = (unsigned)(y0 + 1) < HH;
        bool xv0 = (unsigned)x0 < WW;
        bool xv1 = (unsigned)(x0 + 1) < WW;

        const float* p = vb + (y0 * WW + x0) * CC;
        float v00 = 0.f, v01 = 0.f, v10 = 0.f, v11 = 0.f;
        if (yv0 && xv0) v00 = __ldg(p);
        if (yv0 && xv1) v01 = __ldg(p + CC);
        if (yv1 && xv0) v10 = __ldg(p + WW * CC);
        if (yv1 && xv1) v11 = __ldg(p + WW * CC + CC);

        float wy0 = 1.f - tyf, wx0 = 1.f - txf;
        float bi = wy0 * (wx0 * v00 + txf * v01)
                 + tyf * (wx0 * v10 + txf * v11);
        acc = fmaf(msk, bi, acc);
    }
    sampled[nl * CC + g * 32 + lane] = acc;
}

// ---------------------------------------------------------------------------
extern "C" void kernel_launch(void* const* d_in, const int* in_sizes, int n_in,
                              void* d_out, int out_size)
{
    const float* x   = (const float*)d_in[0];
    const float* dww = (const float*)d_in[1];
    const float* dwb = (const float*)d_in[2];
    const float* omw = (const float*)d_in[3];
    const float* omb = (const float*)d_in[4];
    const float* vpw = (const float*)d_in[5];
    const float* vpb = (const float*)d_in[6];
    const float* opw = (const float*)d_in[7];
    float* out = (float*)d_out;

    float *pval, *pomin, *pom, *psamp;
    cudaGetSymbolAddress((void**)&pval,  g_value);
    cudaGetSymbolAddress((void**)&pomin, g_omin);
    cudaGetSymbolAddress((void**)&pom,   g_om);
    cudaGetSymbolAddress((void**)&psamp, g_samp);

    // 1) value projection: (n,C,L) x -> value (n,L,C)
    gemm_tc<true, false, true><<<dim3(CC / 128, LL / 128, NN), 256>>>(
        x, vpw, vpb, pval, LL, CC, CC);

    // 2) depthwise conv -> om_in (n,C,L)
    dw_k<<<(NN * CC * LL + 255) / 256, 256>>>(x, dww, dwb, pomin);

    // 3) offset/mask projection: om_in -> om (n,L,216)
    gemm_tc<true, false, true><<<dim3((OMC + 127) / 128, LL / 128, NN), 256>>>(
        pomin, omw, omb, pom, LL, OMC, CC);

    // 4) deformable sampling -> sampled (n,L,C)
    samp_k<<<(NN * LL * GG * 32 + 255) / 256, 256>>>(pval, pom, psamp);

    // 5) output projection, write transposed directly to d_out (n,C,H,W)
    gemm_tc<false, true, false><<<dim3(CC / 128, LL / 128, NN), 256>>>(
        psamp, opw, nullptr, out, LL, CC, CC);
}

// round 3
// speedup vs baseline: 2.3099x; 1.2383x over previous
#include <cuda_runtime.h>
#include <cuda_bf16.h>
#include <cstdint>
#include <cstddef>

#define NN 8
#define CC 256
#define HH 64
#define WW 64
#define LL (HH*WW)      // 4096
#define GG 8
#define KK 9
#define OMC (GG*KK*3)   // 216

// Scratch (allocation-free: __device__ globals)
__device__ float g_value[(size_t)NN*LL*CC];   // (n, L, C)
__device__ float g_omin [(size_t)NN*CC*LL];   // (n, C, L)  depthwise output
__device__ float g_om   [(size_t)NN*LL*OMC];  // (n, L, 216)
__device__ float g_samp [(size_t)NN*LL*CC];   // (n, L, C)

// ---------------------------------------------------------------------------
// tf32 helpers
// ---------------------------------------------------------------------------
__device__ __forceinline__ uint32_t f2tf(float f) {
    uint32_t r; asm("cvt.rna.tf32.f32 %0, %1;" : "=r"(r) : "f"(f)); return r;
}
__device__ __forceinline__ void ldsm4(uint32_t addr, uint32_t& r0, uint32_t& r1,
                                      uint32_t& r2, uint32_t& r3) {
    asm volatile("ldmatrix.sync.aligned.m8n8.x4.shared.b16 {%0,%1,%2,%3}, [%4];"
                 : "=r"(r0), "=r"(r1), "=r"(r2), "=r"(r3) : "r"(addr));
}
__device__ __forceinline__ void mma8(float* d, const uint32_t* a, const uint32_t* b) {
    asm volatile("mma.sync.aligned.m16n8k8.row.col.f32.tf32.tf32.f32 "
                 "{%0,%1,%2,%3}, {%4,%5,%6,%7}, {%8,%9}, {%0,%1,%2,%3};"
                 : "+f"(d[0]), "+f"(d[1]), "+f"(d[2]), "+f"(d[3])
                 : "r"(a[0]), "r"(a[1]), "r"(a[2]), "r"(a[3]),
                   "r"(b[0]), "r"(b[1]));
}

// ---------------------------------------------------------------------------
// tf32 tensor-core batched GEMM (same as R2): out[m][j] = sum_k a(m,k)*Wt[j*Kc+k]
// ---------------------------------------------------------------------------
template<bool A_COL, bool OUT_T, bool HAS_BIAS>
__global__ void __launch_bounds__(256)
gemm_tc(const float* __restrict__ A, const float* __restrict__ Wt,
        const float* __restrict__ bias, float* __restrict__ out,
        int M, int Nj, int Kc)
{
    constexpr int BM = 128, BN = 128, BK = 16, PAD = 20;
    __shared__ uint32_t As[2][BM][PAD];
    __shared__ uint32_t Bs[2][BN][PAD];

    const int tid = threadIdx.x;
    const int bz = blockIdx.z;
    A   += (size_t)bz * M * Kc;
    out += (size_t)bz * M * Nj;
    const int m0 = blockIdx.y * BM;
    const int j0 = blockIdx.x * BN;

    int a_m[2], a_k[2];
    const float* a_ptr[2];
    int b_j[2], b_k[2];
    const float* b_ptr[2];
    bool b_ok[2];
    #pragma unroll
    for (int p = 0; p < 2; p++) {
        int lin = (tid + p * 256) * 4;
        if (A_COL) {
            a_m[p] = lin & 127; a_k[p] = lin >> 7;
            a_ptr[p] = A + (size_t)a_k[p] * M + m0 + a_m[p];
        } else {
            a_k[p] = lin & 15;  a_m[p] = lin >> 4;
            a_ptr[p] = A + (size_t)(m0 + a_m[p]) * Kc + a_k[p];
        }
        b_k[p] = lin & 15; b_j[p] = lin >> 4;
        b_ok[p] = (j0 + b_j[p]) < Nj;
        b_ptr[p] = Wt + (size_t)(j0 + b_j[p]) * Kc + b_k[p];
    }

    const int lane = tid & 31, wrp = tid >> 5;
    const int wm = wrp & 1, wn = wrp >> 1;
    const uint32_t as_base = (uint32_t)__cvta_generic_to_shared(&As[0][0][0]);
    const uint32_t bs_base = (uint32_t)__cvta_generic_to_shared(&Bs[0][0][0]);
    const uint32_t BUFB = BM * PAD * 4;

    const int arow = wm * 64 + (lane & 15);
    const int acol = 4 * (lane >> 4);
    const uint32_t aaddr0 = as_base + (uint32_t)(arow * PAD + acol) * 4;
    const int brow = wn * 32 + (lane & 7) + 8 * (lane >> 4);
    const int bcol = 4 * ((lane >> 3) & 1);
    const uint32_t baddr0 = bs_base + (uint32_t)(brow * PAD + bcol) * 4;

    float acc[4][4][4];
    #pragma unroll
    for (int mi = 0; mi < 4; mi++)
        #pragma unroll
        for (int nj = 0; nj < 4; nj++)
            #pragma unroll
            for (int q = 0; q < 4; q++) acc[mi][nj][q] = 0.f;

    const int KT = Kc / BK;
    float4 ra[2], rb[2];

    #pragma unroll
    for (int p = 0; p < 2; p++) {
        ra[p] = *(const float4*)(a_ptr[p]);
        rb[p] = b_ok[p] ? *(const float4*)(b_ptr[p])
                        : make_float4(0.f, 0.f, 0.f, 0.f);
    }
    #pragma unroll
    for (int p = 0; p < 2; p++) {
        if (A_COL) {
            As[0][a_m[p] + 0][a_k[p]] = f2tf(ra[p].x);
            As[0][a_m[p] + 1][a_k[p]] = f2tf(ra[p].y);
            As[0][a_m[p] + 2][a_k[p]] = f2tf(ra[p].z);
            As[0][a_m[p] + 3][a_k[p]] = f2tf(ra[p].w);
        } else {
            uint4 v = make_uint4(f2tf(ra[p].x), f2tf(ra[p].y), f2tf(ra[p].z), f2tf(ra[p].w));
            *(uint4*)&As[0][a_m[p]][a_k[p]] = v;
        }
        uint4 w = make_uint4(f2tf(rb[p].x), f2tf(rb[p].y), f2tf(rb[p].z), f2tf(rb[p].w));
        *(uint4*)&Bs[0][b_j[p]][b_k[p]] = w;
    }
    __syncthreads();

    int buf = 0;
    for (int kt = 0; kt < KT; kt++) {
        if (kt + 1 < KT) {
            #pragma unroll
            for (int p = 0; p < 2; p++) {
                if (A_COL)
                    ra[p] = *(const float4*)(a_ptr[p] + (size_t)(kt + 1) * BK * M);
                else
                    ra[p] = *(const float4*)(a_ptr[p] + (kt + 1) * BK);
                rb[p] = b_ok[p] ? *(const float4*)(b_ptr[p] + (kt + 1) * BK)
                                : make_float4(0.f, 0.f, 0.f, 0.f);
            }
        }

        const uint32_t abase = aaddr0 + buf * BUFB;
        const uint32_t bbase = baddr0 + buf * BUFB;
        #pragma unroll
        for (int kk = 0; kk < 2; kk++) {
            uint32_t a[4][4], b[4][2];
            #pragma unroll
            for (int mi = 0; mi < 4; mi++)
                ldsm4(abase + (uint32_t)(mi * 16 * PAD + kk * 8) * 4,
                      a[mi][0], a[mi][1], a[mi][2], a[mi][3]);
            #pragma unroll
            for (int njp = 0; njp < 2; njp++)
                ldsm4(bbase + (uint32_t)(njp * 16 * PAD + kk * 8) * 4,
                      b[2 * njp][0], b[2 * njp][1], b[2 * njp + 1][0], b[2 * njp + 1][1]);
            #pragma unroll
            for (int mi = 0; mi < 4; mi++)
                #pragma unroll
                for (int nj = 0; nj < 4; nj++)
                    mma8(acc[mi][nj], a[mi], b[nj]);
        }

        if (kt + 1 < KT) {
            int nb = buf ^ 1;
            #pragma unroll
            for (int p = 0; p < 2; p++) {
                if (A_COL) {
                    As[nb][a_m[p] + 0][a_k[p]] = f2tf(ra[p].x);
                    As[nb][a_m[p] + 1][a_k[p]] = f2tf(ra[p].y);
                    As[nb][a_m[p] + 2][a_k[p]] = f2tf(ra[p].z);
                    As[nb][a_m[p] + 3][a_k[p]] = f2tf(ra[p].w);
                } else {
                    uint4 v = make_uint4(f2tf(ra[p].x), f2tf(ra[p].y), f2tf(ra[p].z), f2tf(ra[p].w));
                    *(uint4*)&As[nb][a_m[p]][a_k[p]] = v;
                }
                uint4 w = make_uint4(f2tf(rb[p].x), f2tf(rb[p].y), f2tf(rb[p].z), f2tf(rb[p].w));
                *(uint4*)&Bs[nb][b_j[p]][b_k[p]] = w;
            }
        }
        __syncthreads();
        buf ^= 1;
    }

    const int r = lane >> 2, c = lane & 3;
    #pragma unroll
    for (int mi = 0; mi < 4; mi++) {
        int m = m0 + wm * 64 + mi * 16 + r;
        #pragma unroll
        for (int nj = 0; nj < 4; nj++) {
            int j = j0 + wn * 32 + nj * 8 + 2 * c;
            if (j < Nj) {
                float bj0 = HAS_BIAS ? bias[j]     : 0.f;
                float bj1 = HAS_BIAS ? bias[j + 1] : 0.f;
                float v0 = acc[mi][nj][0] + bj0;
                float v1 = acc[mi][nj][1] + bj1;
                float v2 = acc[mi][nj][2] + bj0;
                float v3 = acc[mi][nj][3] + bj1;
                if (OUT_T) {
                    out[(size_t)j * M + m]           = v0;
                    out[(size_t)(j + 1) * M + m]     = v1;
                    out[(size_t)j * M + m + 8]       = v2;
                    out[(size_t)(j + 1) * M + m + 8] = v3;
                } else {
                    *(float2*)&out[(size_t)m * Nj + j]       = make_float2(v0, v1);
                    *(float2*)&out[(size_t)(m + 8) * Nj + j] = make_float2(v2, v3);
                }
            }
        }
    }
}

// ---------------------------------------------------------------------------
// Depthwise 3x3 conv, SAME padding, float4: one thread = 4 consecutive x.
// x:(N,C,H,W) -> out:(N,C,L)
// ---------------------------------------------------------------------------
__global__ void __launch_bounds__(256)
dw_v4(const float* __restrict__ x, const float* __restrict__ w,
      const float* __restrict__ b, float* __restrict__ out)
{
    int t = blockIdx.x * blockDim.x + threadIdx.x;
    if (t >= NN * CC * HH * (WW / 4)) return;
    int x4 = (t & 15) * 4;          // 0,4,...,60
    int yy = (t >> 4) & (HH - 1);
    int c  = (t >> 10) & (CC - 1);
    int n  = t >> 18;

    const float* base = x + ((size_t)(n * CC + c) * HH) * WW;
    float wc[9];
    #pragma unroll
    for (int i = 0; i < 9; i++) wc[i] = w[c * 9 + i];

    float v[3][6];
    #pragma unroll
    for (int dy = 0; dy < 3; dy++) {
        int row = yy + dy - 1;
        if (row >= 0 && row < HH) {
            const float* rp = base + row * WW + x4;
            v[dy][0] = (x4 > 0) ? rp[-1] : 0.f;
            float4 m = *(const float4*)rp;
            v[dy][1] = m.x; v[dy][2] = m.y; v[dy][3] = m.z; v[dy][4] = m.w;
            v[dy][5] = (x4 + 4 < WW) ? rp[4] : 0.f;
        } else {
            #pragma unroll
            for (int i = 0; i < 6; i++) v[dy][i] = 0.f;
        }
    }

    float bc = b[c];
    float4 o;
    float* op = &o.x;
    #pragma unroll
    for (int i = 0; i < 4; i++) {
        float s = bc;
        #pragma unroll
        for (int dy = 0; dy < 3; dy++)
            #pragma unroll
            for (int dx = 0; dx < 3; dx++)
                s = fmaf(v[dy][i + dx], wc[dy * 3 + dx], s);
        op[i] = s;
    }
    *(float4*)(out + (size_t)((n * CC + c) * HH + yy) * WW + x4) = o;
}

// ---------------------------------------------------------------------------
// Deformable bilinear sampling, float4: one thread = (n, l, g, c4),
// 4 channels per thread. 8 lanes x 16B = one 128B transaction per corner.
// value:(n,L,C), om:(n,L,216) -> sampled:(n,L,C)
// ---------------------------------------------------------------------------
__global__ void __launch_bounds__(256)
samp_v4(const float* __restrict__ value, const float* __restrict__ om,
        float* __restrict__ sampled)
{
    int t = blockIdx.x * blockDim.x + threadIdx.x;
    if (t >= NN * LL * GG * 8) return;
    int c4 = t & 7;                 // float4 chunk within group (32ch = 8 chunks)
    int g  = (t >> 3) & (GG - 1);
    int nl = t >> 6;                // n*L + l
    int l  = nl & (LL - 1);
    int n  = nl >> 12;
    int yy = l >> 6, xx = l & 63;

    const float* omp = om + nl * OMC + g * 27;
    const float* vb  = value + n * (LL * CC) + g * 32 + c4 * 4;

    float ax = 0.f, ay = 0.f, az = 0.f, aw = 0.f;
    #pragma unroll
    for (int k = 0; k < KK; k++) {
        float offy = omp[2 * k];
        float offx = omp[2 * k + 1];
        float msk  = omp[18 + k];
        float py = (float)(yy + k / 3 - 1) + offy;
        float px = (float)(xx + k % 3 - 1) + offx;
        float fy = floorf(py), fx = floorf(px);
        float tyf = py - fy, txf = px - fx;
        int y0 = (int)fy, x0 = (int)fx;

        bool yv0 = (unsigned)y0 < HH;
        bool yv1 = (unsigned)(y0 + 1) < HH;
        bool xv0 = (unsigned)x0 < WW;
        bool xv1 = (unsigned)(x0 + 1) < WW;

        float wy0 = 1.f - tyf, wx0 = 1.f - txf;
        float w00 = msk * wy0 * wx0;
        float w01 = msk * wy0 * txf;
        float w10 = msk * tyf * wx0;
        float w11 = msk * tyf * txf;

        const float* p = vb + (y0 * WW + x0) * CC;
        if (yv0 && xv0) {
            float4 v = *(const float4*)p;
            ax = fmaf(w00, v.x, ax); ay = fmaf(w00, v.y, ay);
            az = fmaf(w00, v.z, az); aw = fmaf(w00, v.w, aw);
        }
        if (yv0 && xv1) {
            float4 v = *(const float4*)(p + CC);
            ax = fmaf(w01, v.x, ax); ay = fmaf(w01, v.y, ay);
            az = fmaf(w01, v.z, az); aw = fmaf(w01, v.w, aw);
        }
        if (yv1 && xv0) {
            float4 v = *(const float4*)(p + WW * CC);
            ax = fmaf(w10, v.x, ax); ay = fmaf(w10, v.y, ay);
            az = fmaf(w10, v.z, az); aw = fmaf(w10, v.w, aw);
        }
        if (yv1 && xv1) {
            float4 v = *(const float4*)(p + WW * CC + CC);
            ax = fmaf(w11, v.x, ax); ay = fmaf(w11, v.y, ay);
            az = fmaf(w11, v.z, az); aw = fmaf(w11, v.w, aw);
        }
    }
    *(float4*)(sampled + nl * CC + g * 32 + c4 * 4) = make_float4(ax, ay, az, aw);
}

// ---------------------------------------------------------------------------
extern "C" void kernel_launch(void* const* d_in, const int* in_sizes, int n_in,
                              void* d_out, int out_size)
{
    const float* x   = (const float*)d_in[0];
    const float* dww = (const float*)d_in[1];
    const float* dwb = (const float*)d_in[2];
    const float* omw = (const float*)d_in[3];
    const float* omb = (const float*)d_in[4];
    const float* vpw = (const float*)d_in[5];
    const float* vpb = (const float*)d_in[6];
    const float* opw = (const float*)d_in[7];
    float* out = (float*)d_out;

    float *pval, *pomin, *pom, *psamp;
    cudaGetSymbolAddress((void**)&pval,  g_value);
    cudaGetSymbolAddress((void**)&pomin, g_omin);
    cudaGetSymbolAddress((void**)&pom,   g_om);
    cudaGetSymbolAddress((void**)&psamp, g_samp);

    // 1) value projection: (n,C,L) x -> value (n,L,C)
    gemm_tc<true, false, true><<<dim3(CC / 128, LL / 128, NN), 256>>>(
        x, vpw, vpb, pval, LL, CC, CC);

    // 2) depthwise conv -> om_in (n,C,L)
    dw_v4<<<(NN * CC * HH * (WW / 4) + 255) / 256, 256>>>(x, dww, dwb, pomin);

    // 3) offset/mask projection: om_in -> om (n,L,216)
    gemm_tc<true, false, true><<<dim3((OMC + 127) / 128, LL / 128, NN), 256>>>(
        pomin, omw, omb, pom, LL, OMC, CC);

    // 4) deformable sampling -> sampled (n,L,C)
    samp_v4<<<(NN * LL * GG * 8 + 255) / 256, 256>>>(pval, pom, psamp);

    // 5) output projection, write transposed directly to d_out (n,C,H,W)
    gemm_tc<false, true, false><<<dim3(CC / 128, LL / 128, NN), 256>>>(
        psamp, opw, nullptr, out, LL, CC, CC);
}

// round 5
// speedup vs baseline: 2.3161x; 1.0027x over previous
#include <cuda_runtime.h>
#include <cuda_bf16.h>
#include <cstdint>
#include <cstddef>

#define NN 8
#define CC 256
#define HH 64
#define WW 64
#define LL (HH*WW)      // 4096
#define GG 8
#define KK 9
#define OMC (GG*KK*3)   // 216

// Scratch (allocation-free: __device__ globals)
__device__ float g_value[(size_t)NN*LL*CC];   // (n, L, C)
__device__ float g_omin [(size_t)NN*CC*LL];   // (n, C, L)  depthwise output
__device__ float g_om   [(size_t)NN*LL*OMC];  // (n, L, 216)
__device__ float g_samp [(size_t)NN*LL*CC];   // (n, L, C)

// ---------------------------------------------------------------------------
// tf32 helpers
// ---------------------------------------------------------------------------
__device__ __forceinline__ uint32_t f2tf(float f) {
    uint32_t r; asm("cvt.rna.tf32.f32 %0, %1;" : "=r"(r) : "f"(f)); return r;
}
__device__ __forceinline__ void ldsm4(uint32_t addr, uint32_t& r0, uint32_t& r1,
                                      uint32_t& r2, uint32_t& r3) {
    asm volatile("ldmatrix.sync.aligned.m8n8.x4.shared.b16 {%0,%1,%2,%3}, [%4];"
                 : "=r"(r0), "=r"(r1), "=r"(r2), "=r"(r3) : "r"(addr));
}
__device__ __forceinline__ void mma8(float* d, const uint32_t* a, const uint32_t* b) {
    asm volatile("mma.sync.aligned.m16n8k8.row.col.f32.tf32.tf32.f32 "
                 "{%0,%1,%2,%3}, {%4,%5,%6,%7}, {%8,%9}, {%0,%1,%2,%3};"
                 : "+f"(d[0]), "+f"(d[1]), "+f"(d[2]), "+f"(d[3])
                 : "r"(a[0]), "r"(a[1]), "r"(a[2]), "r"(a[3]),
                   "r"(b[0]), "r"(b[1]));
}

// ---------------------------------------------------------------------------
// tf32 tensor-core batched GEMM: out[m][j] = sum_k a(m,k)*Wt[j*Kc+k]
// ---------------------------------------------------------------------------
template<bool A_COL, bool OUT_T, bool HAS_BIAS>
__global__ void __launch_bounds__(256)
gemm_tc(const float* __restrict__ A, const float* __restrict__ Wt,
        const float* __restrict__ bias, float* __restrict__ out,
        int M, int Nj, int Kc)
{
    constexpr int BM = 128, BN = 128, BK = 16, PAD = 20;
    __shared__ uint32_t As[2][BM][PAD];
    __shared__ uint32_t Bs[2][BN][PAD];

    const int tid = threadIdx.x;
    const int bz = blockIdx.z;
    A   += (size_t)bz * M * Kc;
    out += (size_t)bz * M * Nj;
    const int m0 = blockIdx.y * BM;
    const int j0 = blockIdx.x * BN;

    int a_m[2], a_k[2];
    const float* a_ptr[2];
    int b_j[2], b_k[2];
    const float* b_ptr[2];
    bool b_ok[2];
    #pragma unroll
    for (int p = 0; p < 2; p++) {
        int lin = (tid + p * 256) * 4;
        if (A_COL) {
            a_m[p] = lin & 127; a_k[p] = lin >> 7;
            a_ptr[p] = A + (size_t)a_k[p] * M + m0 + a_m[p];
        } else {
            a_k[p] = lin & 15;  a_m[p] = lin >> 4;
            a_ptr[p] = A + (size_t)(m0 + a_m[p]) * Kc + a_k[p];
        }
        b_k[p] = lin & 15; b_j[p] = lin >> 4;
        b_ok[p] = (j0 + b_j[p]) < Nj;
        b_ptr[p] = Wt + (size_t)(j0 + b_j[p]) * Kc + b_k[p];
    }

    const int lane = tid & 31, wrp = tid >> 5;
    const int wm = wrp & 1, wn = wrp >> 1;
    const uint32_t as_base = (uint32_t)__cvta_generic_to_shared(&As[0][0][0]);
    const uint32_t bs_base = (uint32_t)__cvta_generic_to_shared(&Bs[0][0][0]);
    const uint32_t BUFB = BM * PAD * 4;

    const int arow = wm * 64 + (lane & 15);
    const int acol = 4 * (lane >> 4);
    const uint32_t aaddr0 = as_base + (uint32_t)(arow * PAD + acol) * 4;
    const int brow = wn * 32 + (lane & 7) + 8 * (lane >> 4);
    const int bcol = 4 * ((lane >> 3) & 1);
    const uint32_t baddr0 = bs_base + (uint32_t)(brow * PAD + bcol) * 4;

    float acc[4][4][4];
    #pragma unroll
    for (int mi = 0; mi < 4; mi++)
        #pragma unroll
        for (int nj = 0; nj < 4; nj++)
            #pragma unroll
            for (int q = 0; q < 4; q++) acc[mi][nj][q] = 0.f;

    const int KT = Kc / BK;
    float4 ra[2], rb[2];

    #pragma unroll
    for (int p = 0; p < 2; p++) {
        ra[p] = *(const float4*)(a_ptr[p]);
        rb[p] = b_ok[p] ? *(const float4*)(b_ptr[p])
                        : make_float4(0.f, 0.f, 0.f, 0.f);
    }
    #pragma unroll
    for (int p = 0; p < 2; p++) {
        if (A_COL) {
            As[0][a_m[p] + 0][a_k[p]] = f2tf(ra[p].x);
            As[0][a_m[p] + 1][a_k[p]] = f2tf(ra[p].y);
            As[0][a_m[p] + 2][a_k[p]] = f2tf(ra[p].z);
            As[0][a_m[p] + 3][a_k[p]] = f2tf(ra[p].w);
        } else {
            uint4 v = make_uint4(f2tf(ra[p].x), f2tf(ra[p].y), f2tf(ra[p].z), f2tf(ra[p].w));
            *(uint4*)&As[0][a_m[p]][a_k[p]] = v;
        }
        uint4 w = make_uint4(f2tf(rb[p].x), f2tf(rb[p].y), f2tf(rb[p].z), f2tf(rb[p].w));
        *(uint4*)&Bs[0][b_j[p]][b_k[p]] = w;
    }
    __syncthreads();

    int buf = 0;
    for (int kt = 0; kt < KT; kt++) {
        if (kt + 1 < KT) {
            #pragma unroll
            for (int p = 0; p < 2; p++) {
                if (A_COL)
                    ra[p] = *(const float4*)(a_ptr[p] + (size_t)(kt + 1) * BK * M);
                else
                    ra[p] = *(const float4*)(a_ptr[p] + (kt + 1) * BK);
                rb[p] = b_ok[p] ? *(const float4*)(b_ptr[p] + (kt + 1) * BK)
                                : make_float4(0.f, 0.f, 0.f, 0.f);
            }
        }

        const uint32_t abase = aaddr0 + buf * BUFB;
        const uint32_t bbase = baddr0 + buf * BUFB;
        #pragma unroll
        for (int kk = 0; kk < 2; kk++) {
            uint32_t a[4][4], b[4][2];
            #pragma unroll
            for (int mi = 0; mi < 4; mi++)
                ldsm4(abase + (uint32_t)(mi * 16 * PAD + kk * 8) * 4,
                      a[mi][0], a[mi][1], a[mi][2], a[mi][3]);
            #pragma unroll
            for (int njp = 0; njp < 2; njp++)
                ldsm4(bbase + (uint32_t)(njp * 16 * PAD + kk * 8) * 4,
                      b[2 * njp][0], b[2 * njp][1], b[2 * njp + 1][0], b[2 * njp + 1][1]);
            #pragma unroll
            for (int mi = 0; mi < 4; mi++)
                #pragma unroll
                for (int nj = 0; nj < 4; nj++)
                    mma8(acc[mi][nj], a[mi], b[nj]);
        }

        if (kt + 1 < KT) {
            int nb = buf ^ 1;
            #pragma unroll
            for (int p = 0; p < 2; p++) {
                if (A_COL) {
                    As[nb][a_m[p] + 0][a_k[p]] = f2tf(ra[p].x);
                    As[nb][a_m[p] + 1][a_k[p]] = f2tf(ra[p].y);
                    As[nb][a_m[p] + 2][a_k[p]] = f2tf(ra[p].z);
                    As[nb][a_m[p] + 3][a_k[p]] = f2tf(ra[p].w);
                } else {
                    uint4 v = make_uint4(f2tf(ra[p].x), f2tf(ra[p].y), f2tf(ra[p].z), f2tf(ra[p].w));
                    *(uint4*)&As[nb][a_m[p]][a_k[p]] = v;
                }
                uint4 w = make_uint4(f2tf(rb[p].x), f2tf(rb[p].y), f2tf(rb[p].z), f2tf(rb[p].w));
                *(uint4*)&Bs[nb][b_j[p]][b_k[p]] = w;
            }
        }
        __syncthreads();
        buf ^= 1;
    }

    const int r = lane >> 2, c = lane & 3;
    #pragma unroll
    for (int mi = 0; mi < 4; mi++) {
        int m = m0 + wm * 64 + mi * 16 + r;
        #pragma unroll
        for (int nj = 0; nj < 4; nj++) {
            int j = j0 + wn * 32 + nj * 8 + 2 * c;
            if (j < Nj) {
                float bj0 = HAS_BIAS ? bias[j]     : 0.f;
                float bj1 = HAS_BIAS ? bias[j + 1] : 0.f;
                float v0 = acc[mi][nj][0] + bj0;
                float v1 = acc[mi][nj][1] + bj1;
                float v2 = acc[mi][nj][2] + bj0;
                float v3 = acc[mi][nj][3] + bj1;
                if (OUT_T) {
                    out[(size_t)j * M + m]           = v0;
                    out[(size_t)(j + 1) * M + m]     = v1;
                    out[(size_t)j * M + m + 8]       = v2;
                    out[(size_t)(j + 1) * M + m + 8] = v3;
                } else {
                    *(float2*)&out[(size_t)m * Nj + j]       = make_float2(v0, v1);
                    *(float2*)&out[(size_t)(m + 8) * Nj + j] = make_float2(v2, v3);
                }
            }
        }
    }
}

// ---------------------------------------------------------------------------
// Depthwise 3x3 conv, SAME padding, float4: one thread = 4 consecutive x.
// ---------------------------------------------------------------------------
__global__ void __launch_bounds__(256)
dw_v4(const float* __restrict__ x, const float* __restrict__ w,
      const float* __restrict__ b, float* __restrict__ out)
{
    int t = blockIdx.x * blockDim.x + threadIdx.x;
    if (t >= NN * CC * HH * (WW / 4)) return;
    int x4 = (t & 15) * 4;
    int yy = (t >> 4) & (HH - 1);
    int c  = (t >> 10) & (CC - 1);
    int n  = t >> 18;

    const float* base = x + ((size_t)(n * CC + c) * HH) * WW;
    float wc[9];
    #pragma unroll
    for (int i = 0; i < 9; i++) wc[i] = w[c * 9 + i];

    float v[3][6];
    #pragma unroll
    for (int dy = 0; dy < 3; dy++) {
        int row = yy + dy - 1;
        if (row >= 0 && row < HH) {
            const float* rp = base + row * WW + x4;
            v[dy][0] = (x4 > 0) ? rp[-1] : 0.f;
            float4 m = *(const float4*)rp;
            v[dy][1] = m.x; v[dy][2] = m.y; v[dy][3] = m.z; v[dy][4] = m.w;
            v[dy][5] = (x4 + 4 < WW) ? rp[4] : 0.f;
        } else {
            #pragma unroll
            for (int i = 0; i < 6; i++) v[dy][i] = 0.f;
        }
    }

    float bc = b[c];
    float4 o;
    float* op = &o.x;
    #pragma unroll
    for (int i = 0; i < 4; i++) {
        float s = bc;
        #pragma unroll
        for (int dy = 0; dy < 3; dy++)
            #pragma unroll
            for (int dx = 0; dx < 3; dx++)
                s = fmaf(v[dy][i + dx], wc[dy * 3 + dx], s);
        op[i] = s;
    }
    *(float4*)(out + (size_t)((n * CC + c) * HH + yy) * WW + x4) = o;
}

// ---------------------------------------------------------------------------
// Deformable bilinear sampling, two-phase.
// Block = 256 threads = 4 (n,l) points x 64 threads (8 g x 8 c4-chunks).
// Phase 1: 288 weight records (p,g,k) computed once into smem:
//          mask-folded bilinear weights with validity folded in, and a base
//          index clamped so all 4 corner loads are unconditional & in-bounds.
// Phase 2: pure float4 gathers + FMAs; weights read via LDS broadcast.
// ---------------------------------------------------------------------------
__global__ void __launch_bounds__(256)
samp_sm(const float* __restrict__ value, const float* __restrict__ om,
        float* __restrict__ sampled)
{
    __shared__ float s_w00[288], s_w01[288], s_w10[288], s_w11[288];
    __shared__ int   s_ib[288];

    const int tid = threadIdx.x;
    const int nl0 = blockIdx.x * 4;

    // ---- phase 1: one record per (p, g, k) ----
    for (int rec = tid; rec < 288; rec += 256) {
        int p  = rec / 72;
        int gk = rec - p * 72;
        int g  = gk / 9;
        int k  = gk - g * 9;
        int nl = nl0 + p;
        int l  = nl & (LL - 1);
        int yy = l >> 6, xx = l & 63;

        const float* omp = om + nl * OMC + g * 27;
        float offy = omp[2 * k];
        float offx = omp[2 * k + 1];
        float msk  = omp[18 + k];

        float py = (float)(yy + k / 3 - 1) + offy;
        float px = (float)(xx + k % 3 - 1) + offx;
        float fy = floorf(py), fx = floorf(px);
        float ty = py - fy, tx = px - fx;
        int y0 = (int)fy, x0 = (int)fx;
        int y0c = min(max(y0, 0), HH - 2);
        int x0c = min(max(x0, 0), WW - 2);

        // weights of the clamped 2x2 box rows/cols, validity folded in:
        //  row y0c gets: (1-ty) if y0==y0c;  ty if y0+1==y0c;  else 0
        //  row y0c+1 gets: (1-ty) if y0==y0c+1;  ty if y0+1==y0c+1 (in-bounds); else 0
        float wr0 = (y0 == y0c) ? (1.f - ty) : ((y0 + 1 == y0c) ? ty : 0.f);
        float wr1 = (y0 == y0c + 1) ? (1.f - ty)
                  : ((y0 == y0c && y0 + 1 < HH) ? ty : 0.f);
        float wc0 = (x0 == x0c) ? (1.f - tx) : ((x0 + 1 == x0c) ? tx : 0.f);
        float wc1 = (x0 == x0c + 1) ? (1.f - tx)
                  : ((x0 == x0c && x0 + 1 < WW) ? tx : 0.f);

        s_w00[rec] = msk * wr0 * wc0;
        s_w01[rec] = msk * wr0 * wc1;
        s_w10[rec] = msk * wr1 * wc0;
        s_w11[rec] = msk * wr1 * wc1;
        s_ib[rec]  = (y0c * WW + x0c) * CC;
    }
    __syncthreads();

    // ---- phase 2: pure gathers ----
    const int p  = tid >> 6;
    const int lo = tid & 63;
    const int g  = lo >> 3;
    const int c4 = lo & 7;
    const int nl = nl0 + p;
    const int n  = nl >> 12;

    const float* vb = value + n * (LL * CC) + g * 32 + c4 * 4;
    const int rb = p * 72 + g * 9;

    float ax = 0.f, ay = 0.f, az = 0.f, aw = 0.f;
    #pragma unroll
    for (int k = 0; k < KK; k++) {
        float w00 = s_w00[rb + k];
        float w01 = s_w01[rb + k];
        float w10 = s_w10[rb + k];
        float w11 = s_w11[rb + k];
        const float* pp = vb + s_ib[rb + k];

        float4 v00 = *(const float4*)pp;
        float4 v01 = *(const float4*)(pp + CC);
        float4 v10 = *(const float4*)(pp + WW * CC);
        float4 v11 = *(const float4*)(pp + WW * CC + CC);

        ax = fmaf(w00, v00.x, ax); ay = fmaf(w00, v00.y, ay);
        az = fmaf(w00, v00.z, az); aw = fmaf(w00, v00.w, aw);
        ax = fmaf(w01, v01.x, ax); ay = fmaf(w01, v01.y, ay);
        az = fmaf(w01, v01.z, az); aw = fmaf(w01, v01.w, aw);
        ax = fmaf(w10, v10.x, ax); ay = fmaf(w10, v10.y, ay);
        az = fmaf(w10, v10.z, az); aw = fmaf(w10, v10.w, aw);
        ax = fmaf(w11, v11.x, ax); ay = fmaf(w11, v11.y, ay);
        az = fmaf(w11, v11.z, az); aw = fmaf(w11, v11.w, aw);
    }
    *(float4*)(sampled + nl * CC + g * 32 + c4 * 4) = make_float4(ax, ay, az, aw);
}

// ---------------------------------------------------------------------------
extern "C" void kernel_launch(void* const* d_in, const int* in_sizes, int n_in,
                              void* d_out, int out_size)
{
    const float* x   = (const float*)d_in[0];
    const float* dww = (const float*)d_in[1];
    const float* dwb = (const float*)d_in[2];
    const float* omw = (const float*)d_in[3];
    const float* omb = (const float*)d_in[4];
    const float* vpw = (const float*)d_in[5];
    const float* vpb = (const float*)d_in[6];
    const float* opw = (const float*)d_in[7];
    float* out = (float*)d_out;

    float *pval, *pomin, *pom, *psamp;
    cudaGetSymbolAddress((void**)&pval,  g_value);
    cudaGetSymbolAddress((void**)&pomin, g_omin);
    cudaGetSymbolAddress((void**)&pom,   g_om);
    cudaGetSymbolAddress((void**)&psamp, g_samp);

    // 1) value projection: (n,C,L) x -> value (n,L,C)
    gemm_tc<true, false, true><<<dim3(CC / 128, LL / 128, NN), 256>>>(
        x, vpw, vpb, pval, LL, CC, CC);

    // 2) depthwise conv -> om_in (n,C,L)
    dw_v4<<<(NN * CC * HH * (WW / 4) + 255) / 256, 256>>>(x, dww, dwb, pomin);

    // 3) offset/mask projection: om_in -> om (n,L,216)
    gemm_tc<true, false, true><<<dim3((OMC + 127) / 128, LL / 128, NN), 256>>>(
        pomin, omw, omb, pom, LL, OMC, CC);

    // 4) deformable sampling -> sampled (n,L,C)
    samp_sm<<<NN * LL / 4, 256>>>(pval, pom, psamp);

    // 5) output projection, write transposed directly to d_out (n,C,H,W)
    gemm_tc<false, true, false><<<dim3(CC / 128, LL / 128, NN), 256>>>(
        psamp, opw, nullptr, out, LL, CC, CC);
}

// round 6
// speedup vs baseline: 2.8680x; 1.2383x over previous
#include <cuda_runtime.h>
#include <cuda_bf16.h>
#include <cstdint>
#include <cstddef>

#define NN 8
#define CC 256
#define HH 64
#define WW 64
#define LL (HH*WW)      // 4096
#define GG 8
#define KK 9
#define OMC (GG*KK*3)   // 216

// Scratch (allocation-free: __device__ globals)
__device__ float g_value[(size_t)NN*LL*CC];   // (n, L, C)
__device__ float g_omin [(size_t)NN*CC*LL];   // (n, C, L)  depthwise output
__device__ float g_om   [(size_t)NN*LL*OMC];  // (n, L, 216)
__device__ float g_samp [(size_t)NN*LL*CC];   // (n, L, C)

// ---------------------------------------------------------------------------
// tf32 helpers
// ---------------------------------------------------------------------------
__device__ __forceinline__ uint32_t f2tf(float f) {
    uint32_t r; asm("cvt.rna.tf32.f32 %0, %1;" : "=r"(r) : "f"(f)); return r;
}
__device__ __forceinline__ void ldsm4(uint32_t addr, uint32_t& r0, uint32_t& r1,
                                      uint32_t& r2, uint32_t& r3) {
    asm volatile("ldmatrix.sync.aligned.m8n8.x4.shared.b16 {%0,%1,%2,%3}, [%4];"
                 : "=r"(r0), "=r"(r1), "=r"(r2), "=r"(r3) : "r"(addr));
}
__device__ __forceinline__ void mma8(float* d, const uint32_t* a, const uint32_t* b) {
    asm volatile("mma.sync.aligned.m16n8k8.row.col.f32.tf32.tf32.f32 "
                 "{%0,%1,%2,%3}, {%4,%5,%6,%7}, {%8,%9}, {%0,%1,%2,%3};"
                 : "+f"(d[0]), "+f"(d[1]), "+f"(d[2]), "+f"(d[3])
                 : "r"(a[0]), "r"(a[1]), "r"(a[2]), "r"(a[3]),
                   "r"(b[0]), "r"(b[1]));
}

// ---------------------------------------------------------------------------
// tf32 tensor-core batched GEMM: out[m][j] = sum_k a(m,k)*Wt[j*Kc+k]
//   A_COL : a(m,k) = A[k*M + m]  -> staged via 4x coalesced LDG.32 along k and
//           ONE conflict-free STS.128 per chunk (fixes 16-way bank conflict)
//   !A_COL: a(m,k) = A[m*Kc + k] (row-major, STS.128 path)
// ---------------------------------------------------------------------------
template<bool A_COL, bool OUT_T, bool HAS_BIAS>
__global__ void __launch_bounds__(256)
gemm_tc(const float* __restrict__ A, const float* __restrict__ Wt,
        const float* __restrict__ bias, float* __restrict__ out,
        int M, int Nj, int Kc)
{
    constexpr int BM = 128, BN = 128, BK = 16, PAD = 20;
    __shared__ uint32_t As[2][BM][PAD];
    __shared__ uint32_t Bs[2][BN][PAD];

    const int tid = threadIdx.x;
    const int bz = blockIdx.z;
    A   += (size_t)bz * M * Kc;
    out += (size_t)bz * M * Nj;
    const int m0 = blockIdx.y * BM;
    const int j0 = blockIdx.x * BN;

    // ---- staging address setup (2 chunks per thread per operand) ----
    int a_m[2], a_k[2];
    const float* a_ptr[2];
    int b_j[2], b_k[2];
    const float* b_ptr[2];
    bool b_ok[2];
    #pragma unroll
    for (int p = 0; p < 2; p++) {
        int q = tid + p * 256;          // chunk id 0..511
        if (A_COL) {
            // chunk = (m, k4): m = q&127 (consecutive across lanes -> coalesced),
            // k = 4*(q>>7). Loads: 4 scalar LDGs along k; store: one STS.128.
            a_m[p] = q & 127;
            a_k[p] = (q >> 7) * 4;
            a_ptr[p] = A + (size_t)a_k[p] * M + m0 + a_m[p];
        } else {
            int lin = q * 4;
            a_k[p] = lin & 15;  a_m[p] = lin >> 4;
            a_ptr[p] = A + (size_t)(m0 + a_m[p]) * Kc + a_k[p];
        }
        int lin = q * 4;
        b_k[p] = lin & 15; b_j[p] = lin >> 4;
        b_ok[p] = (j0 + b_j[p]) < Nj;
        b_ptr[p] = Wt + (size_t)(j0 + b_j[p]) * Kc + b_k[p];
    }

    const int lane = tid & 31, wrp = tid >> 5;
    const int wm = wrp & 1, wn = wrp >> 1;
    const uint32_t as_base = (uint32_t)__cvta_generic_to_shared(&As[0][0][0]);
    const uint32_t bs_base = (uint32_t)__cvta_generic_to_shared(&Bs[0][0][0]);
    const uint32_t BUFB = BM * PAD * 4;

    const int arow = wm * 64 + (lane & 15);
    const int acol = 4 * (lane >> 4);
    const uint32_t aaddr0 = as_base + (uint32_t)(arow * PAD + acol) * 4;
    const int brow = wn * 32 + (lane & 7) + 8 * (lane >> 4);
    const int bcol = 4 * ((lane >> 3) & 1);
    const uint32_t baddr0 = bs_base + (uint32_t)(brow * PAD + bcol) * 4;

    float acc[4][4][4];
    #pragma unroll
    for (int mi = 0; mi < 4; mi++)
        #pragma unroll
        for (int nj = 0; nj < 4; nj++)
            #pragma unroll
            for (int q = 0; q < 4; q++) acc[mi][nj][q] = 0.f;

    const int KT = Kc / BK;
    float ra[2][4];
    float4 rb[2];

    // ---- prologue: stage tile 0 into buffer 0 ----
    #pragma unroll
    for (int p = 0; p < 2; p++) {
        if (A_COL) {
            #pragma unroll
            for (int j = 0; j < 4; j++)
                ra[p][j] = a_ptr[p][(size_t)j * M];
        } else {
            float4 v = *(const float4*)(a_ptr[p]);
            ra[p][0] = v.x; ra[p][1] = v.y; ra[p][2] = v.z; ra[p][3] = v.w;
        }
        rb[p] = b_ok[p] ? *(const float4*)(b_ptr[p])
                        : make_float4(0.f, 0.f, 0.f, 0.f);
    }
    #pragma unroll
    for (int p = 0; p < 2; p++) {
        uint4 v = make_uint4(f2tf(ra[p][0]), f2tf(ra[p][1]),
                             f2tf(ra[p][2]), f2tf(ra[p][3]));
        *(uint4*)&As[0][a_m[p]][a_k[p]] = v;   // STS.128, conflict-free
        uint4 w = make_uint4(f2tf(rb[p].x), f2tf(rb[p].y),
                             f2tf(rb[p].z), f2tf(rb[p].w));
        *(uint4*)&Bs[0][b_j[p]][b_k[p]] = w;
    }
    __syncthreads();

    int buf = 0;
    for (int kt = 0; kt < KT; kt++) {
        // prefetch next tile into registers (overlaps with MMA below)
        if (kt + 1 < KT) {
            #pragma unroll
            for (int p = 0; p < 2; p++) {
                if (A_COL) {
                    const float* ap = a_ptr[p] + (size_t)(kt + 1) * BK * M;
                    #pragma unroll
                    for (int j = 0; j < 4; j++)
                        ra[p][j] = ap[(size_t)j * M];
                } else {
                    float4 v = *(const float4*)(a_ptr[p] + (kt + 1) * BK);
                    ra[p][0] = v.x; ra[p][1] = v.y; ra[p][2] = v.z; ra[p][3] = v.w;
                }
                rb[p] = b_ok[p] ? *(const float4*)(b_ptr[p] + (kt + 1) * BK)
                                : make_float4(0.f, 0.f, 0.f, 0.f);
            }
        }

        // compute on current buffer
        const uint32_t abase = aaddr0 + buf * BUFB;
        const uint32_t bbase = baddr0 + buf * BUFB;
        #pragma unroll
        for (int kk = 0; kk < 2; kk++) {
            uint32_t a[4][4], b[4][2];
            #pragma unroll
            for (int mi = 0; mi < 4; mi++)
                ldsm4(abase + (uint32_t)(mi * 16 * PAD + kk * 8) * 4,
                      a[mi][0], a[mi][1], a[mi][2], a[mi][3]);
            #pragma unroll
            for (int njp = 0; njp < 2; njp++)
                ldsm4(bbase + (uint32_t)(njp * 16 * PAD + kk * 8) * 4,
                      b[2 * njp][0], b[2 * njp][1], b[2 * njp + 1][0], b[2 * njp + 1][1]);
            #pragma unroll
            for (int mi = 0; mi < 4; mi++)
                #pragma unroll
                for (int nj = 0; nj < 4; nj++)
                    mma8(acc[mi][nj], a[mi], b[nj]);
        }

        // store prefetched tile into other buffer
        if (kt + 1 < KT) {
            int nb = buf ^ 1;
            #pragma unroll
            for (int p = 0; p < 2; p++) {
                uint4 v = make_uint4(f2tf(ra[p][0]), f2tf(ra[p][1]),
                                     f2tf(ra[p][2]), f2tf(ra[p][3]));
                *(uint4*)&As[nb][a_m[p]][a_k[p]] = v;
                uint4 w = make_uint4(f2tf(rb[p].x), f2tf(rb[p].y),
                                     f2tf(rb[p].z), f2tf(rb[p].w));
                *(uint4*)&Bs[nb][b_j[p]][b_k[p]] = w;
            }
        }
        __syncthreads();
        buf ^= 1;
    }

    // ---- epilogue ----
    const int r = lane >> 2, c = lane & 3;
    #pragma unroll
    for (int mi = 0; mi < 4; mi++) {
        int m = m0 + wm * 64 + mi * 16 + r;
        #pragma unroll
        for (int nj = 0; nj < 4; nj++) {
            int j = j0 + wn * 32 + nj * 8 + 2 * c;
            if (j < Nj) {
                float bj0 = HAS_BIAS ? bias[j]     : 0.f;
                float bj1 = HAS_BIAS ? bias[j + 1] : 0.f;
                float v0 = acc[mi][nj][0] + bj0;
                float v1 = acc[mi][nj][1] + bj1;
                float v2 = acc[mi][nj][2] + bj0;
                float v3 = acc[mi][nj][3] + bj1;
                if (OUT_T) {
                    out[(size_t)j * M + m]           = v0;
                    out[(size_t)(j + 1) * M + m]     = v1;
                    out[(size_t)j * M + m + 8]       = v2;
                    out[(size_t)(j + 1) * M + m + 8] = v3;
                } else {
                    *(float2*)&out[(size_t)m * Nj + j]       = make_float2(v0, v1);
                    *(float2*)&out[(size_t)(m + 8) * Nj + j] = make_float2(v2, v3);
                }
            }
        }
    }
}

// ---------------------------------------------------------------------------
// Depthwise 3x3 conv, SAME padding, float4: one thread = 4 consecutive x.
// ---------------------------------------------------------------------------
__global__ void __launch_bounds__(256)
dw_v4(const float* __restrict__ x, const float* __restrict__ w,
      const float* __restrict__ b, float* __restrict__ out)
{
    int t = blockIdx.x * blockDim.x + threadIdx.x;
    if (t >= NN * CC * HH * (WW / 4)) return;
    int x4 = (t & 15) * 4;
    int yy = (t >> 4) & (HH - 1);
    int c  = (t >> 10) & (CC - 1);
    int n  = t >> 18;

    const float* base = x + ((size_t)(n * CC + c) * HH) * WW;
    float wc[9];
    #pragma unroll
    for (int i = 0; i < 9; i++) wc[i] = w[c * 9 + i];

    float v[3][6];
    #pragma unroll
    for (int dy = 0; dy < 3; dy++) {
        int row = yy + dy - 1;
        if (row >= 0 && row < HH) {
            const float* rp = base + row * WW + x4;
            v[dy][0] = (x4 > 0) ? rp[-1] : 0.f;
            float4 m = *(const float4*)rp;
            v[dy][1] = m.x; v[dy][2] = m.y; v[dy][3] = m.z; v[dy][4] = m.w;
            v[dy][5] = (x4 + 4 < WW) ? rp[4] : 0.f;
        } else {
            #pragma unroll
            for (int i = 0; i < 6; i++) v[dy][i] = 0.f;
        }
    }

    float bc = b[c];
    float4 o;
    float* op = &o.x;
    #pragma unroll
    for (int i = 0; i < 4; i++) {
        float s = bc;
        #pragma unroll
        for (int dy = 0; dy < 3; dy++)
            #pragma unroll
            for (int dx = 0; dx < 3; dx++)
                s = fmaf(v[dy][i + dx], wc[dy * 3 + dx], s);
        op[i] = s;
    }
    *(float4*)(out + (size_t)((n * CC + c) * HH + yy) * WW + x4) = o;
}

// ---------------------------------------------------------------------------
// Deformable bilinear sampling, float4: one thread = (n, l, g, c4),
// 4 channels per thread. 8 lanes x 16B = one 128B transaction per corner.
// ---------------------------------------------------------------------------
__global__ void __launch_bounds__(256)
samp_v4(const float* __restrict__ value, const float* __restrict__ om,
        float* __restrict__ sampled)
{
    int t = blockIdx.x * blockDim.x + threadIdx.x;
    if (t >= NN * LL * GG * 8) return;
    int c4 = t & 7;
    int g  = (t >> 3) & (GG - 1);
    int nl = t >> 6;
    int l  = nl & (LL - 1);
    int n  = nl >> 12;
    int yy = l >> 6, xx = l & 63;

    const float* omp = om + nl * OMC + g * 27;
    const float* vb  = value + n * (LL * CC) + g * 32 + c4 * 4;

    float ax = 0.f, ay = 0.f, az = 0.f, aw = 0.f;
    #pragma unroll
    for (int k = 0; k < KK; k++) {
        float offy = omp[2 * k];
        float offx = omp[2 * k + 1];
        float msk  = omp[18 + k];
        float py = (float)(yy + k / 3 - 1) + offy;
        float px = (float)(xx + k % 3 - 1) + offx;
        float fy = floorf(py), fx = floorf(px);
        float tyf = py - fy, txf = px - fx;
        int y0 = (int)fy, x0 = (int)fx;

        bool yv0 = (unsigned)y0 < HH;
        bool yv1 = (unsigned)(y0 + 1) < HH;
        bool xv0 = (unsigned)x0 < WW;
        bool xv1 = (unsigned)(x0 + 1) < WW;

        float wy0 = 1.f - tyf, wx0 = 1.f - txf;
        float w00 = msk * wy0 * wx0;
        float w01 = msk * wy0 * txf;
        float w10 = msk * tyf * wx0;
        float w11 = msk * tyf * txf;

        const float* p = vb + (y0 * WW + x0) * CC;
        if (yv0 && xv0) {
            float4 v = *(const float4*)p;
            ax = fmaf(w00, v.x, ax); ay = fmaf(w00, v.y, ay);
            az = fmaf(w00, v.z, az); aw = fmaf(w00, v.w, aw);
        }
        if (yv0 && xv1) {
            float4 v = *(const float4*)(p + CC);
            ax = fmaf(w01, v.x, ax); ay = fmaf(w01, v.y, ay);
            az = fmaf(w01, v.z, az); aw = fmaf(w01, v.w, aw);
        }
        if (yv1 && xv0) {
            float4 v = *(const float4*)(p + WW * CC);
            ax = fmaf(w10, v.x, ax); ay = fmaf(w10, v.y, ay);
            az = fmaf(w10, v.z, az); aw = fmaf(w10, v.w, aw);
        }
        if (yv1 && xv1) {
            float4 v = *(const float4*)(p + WW * CC + CC);
            ax = fmaf(w11, v.x, ax); ay = fmaf(w11, v.y, ay);
            az = fmaf(w11, v.z, az); aw = fmaf(w11, v.w, aw);
        }
    }
    *(float4*)(sampled + nl * CC + g * 32 + c4 * 4) = make_float4(ax, ay, az, aw);
}

// ---------------------------------------------------------------------------
extern "C" void kernel_launch(void* const* d_in, const int* in_sizes, int n_in,
                              void* d_out, int out_size)
{
    const float* x   = (const float*)d_in[0];
    const float* dww = (const float*)d_in[1];
    const float* dwb = (const float*)d_in[2];
    const float* omw = (const float*)d_in[3];
    const float* omb = (const float*)d_in[4];
    const float* vpw = (const float*)d_in[5];
    const float* vpb = (const float*)d_in[6];
    const float* opw = (const float*)d_in[7];
    float* out = (float*)d_out;

    float *pval, *pomin, *pom, *psamp;
    cudaGetSymbolAddress((void**)&pval,  g_value);
    cudaGetSymbolAddress((void**)&pomin, g_omin);
    cudaGetSymbolAddress((void**)&pom,   g_om);
    cudaGetSymbolAddress((void**)&psamp, g_samp);

    // 1) value projection: (n,C,L) x -> value (n,L,C)
    gemm_tc<true, false, true><<<dim3(CC / 128, LL / 128, NN), 256>>>(
        x, vpw, vpb, pval, LL, CC, CC);

    // 2) depthwise conv -> om_in (n,C,L)
    dw_v4<<<(NN * CC * HH * (WW / 4) + 255) / 256, 256>>>(x, dww, dwb, pomin);

    // 3) offset/mask projection: om_in -> om (n,L,216)
    gemm_tc<true, false, true><<<dim3((OMC + 127) / 128, LL / 128, NN), 256>>>(
        pomin, omw, omb, pom, LL, OMC, CC);

    // 4) deformable sampling -> sampled (n,L,C)
    samp_v4<<<(NN * LL * GG * 8 + 255) / 256, 256>>>(pval, pom, psamp);

    // 5) output projection, write transposed directly to d_out (n,C,H,W)
    gemm_tc<false, true, false><<<dim3(CC / 128, LL / 128, NN), 256>>>(
        psamp, opw, nullptr, out, LL, CC, CC);
}

// round 7
// speedup vs baseline: 3.3412x; 1.1650x over previous
#include <cuda_runtime.h>
#include <cuda_fp16.h>
#include <cstdint>
#include <cstddef>

#define NN 8
#define CC 256
#define HH 64
#define WW 64
#define LL (HH*WW)      // 4096
#define GG 8
#define KK 9
#define OMC (GG*KK*3)   // 216

// Scratch (allocation-free: __device__ globals)
__device__ float g_value[(size_t)NN*LL*CC];   // (n, L, C)
__device__ float g_omin [(size_t)NN*CC*LL];   // (n, C, L)  depthwise output
__device__ float g_om   [(size_t)NN*LL*OMC];  // (n, L, 216)
__device__ float g_samp [(size_t)NN*LL*CC];   // (n, L, C)

// ---------------------------------------------------------------------------
// fp16 helpers
// ---------------------------------------------------------------------------
__device__ __forceinline__ uint32_t f2h2(float lo, float hi) {
    __half2 h = __floats2half2_rn(lo, hi);
    return *(uint32_t*)&h;
}
__device__ __forceinline__ void ldsm4(uint32_t addr, uint32_t& r0, uint32_t& r1,
                                      uint32_t& r2, uint32_t& r3) {
    asm volatile("ldmatrix.sync.aligned.m8n8.x4.shared.b16 {%0,%1,%2,%3}, [%4];"
                 : "=r"(r0), "=r"(r1), "=r"(r2), "=r"(r3) : "r"(addr));
}
__device__ __forceinline__ void mma16(float* d, const uint32_t* a, const uint32_t* b) {
    asm volatile("mma.sync.aligned.m16n8k16.row.col.f32.f16.f16.f32 "
                 "{%0,%1,%2,%3}, {%4,%5,%6,%7}, {%8,%9}, {%0,%1,%2,%3};"
                 : "+f"(d[0]), "+f"(d[1]), "+f"(d[2]), "+f"(d[3])
                 : "r"(a[0]), "r"(a[1]), "r"(a[2]), "r"(a[3]),
                   "r"(b[0]), "r"(b[1]));
}

// ---------------------------------------------------------------------------
// fp16 tensor-core batched GEMM (fp32 accumulate):
//   out[m][j] = sum_k a(m,k)*Wt[j*Kc+k] (+bias)
//   A_COL : a(m,k) = A[k*M + m]  (coalesced 4xLDG.32 along k, STS.64)
//   !A_COL: a(m,k) = A[m*Kc + k] (LDG.128, STS.64)
// BM=BN=128, BK=16, 256 threads (8 warps, 2x4 grid, 64x32 warp tile).
// smem: half, row stride 40 halves (80B = 20 words): rows 16B-aligned,
// conflict-free ldmatrix ({0,20,8,28,16,4,24,12} bank walk).
// m16n8k16: per warp per k-tile = 4 A-ldsm + 2 B-ldsm + 16 mma.
// ---------------------------------------------------------------------------
template<bool A_COL, bool OUT_T, bool HAS_BIAS>
__global__ void __launch_bounds__(256)
gemm_hc(const float* __restrict__ A, const float* __restrict__ Wt,
        const float* __restrict__ bias, float* __restrict__ out,
        int M, int Nj, int Kc)
{
    constexpr int BM = 128, BN = 128, BK = 16, PADH = 40;
    __shared__ __half As[2][BM][PADH];
    __shared__ __half Bs[2][BN][PADH];

    const int tid = threadIdx.x;
    const int bz = blockIdx.z;
    A   += (size_t)bz * M * Kc;
    out += (size_t)bz * M * Nj;
    const int m0 = blockIdx.y * BM;
    const int j0 = blockIdx.x * BN;

    // ---- staging setup: 2 chunks/thread/operand; chunk = (row, 4 k-values) --
    int a_m[2], a_k[2];
    const float* a_ptr[2];
    int b_j[2], b_k[2];
    const float* b_ptr[2];
    bool b_ok[2];
    #pragma unroll
    for (int p = 0; p < 2; p++) {
        int q = tid + p * 256;          // chunk id 0..511
        if (A_COL) {
            a_m[p] = q & 127;           // consecutive m across lanes -> coalesced
            a_k[p] = (q >> 7) * 4;
            a_ptr[p] = A + (size_t)a_k[p] * M + m0 + a_m[p];
        } else {
            int lin = q * 4;
            a_k[p] = lin & 15;  a_m[p] = lin >> 4;
            a_ptr[p] = A + (size_t)(m0 + a_m[p]) * Kc + a_k[p];
        }
        int lin = q * 4;
        b_k[p] = lin & 15; b_j[p] = lin >> 4;
        b_ok[p] = (j0 + b_j[p]) < Nj;
        b_ptr[p] = Wt + (size_t)(j0 + b_j[p]) * Kc + b_k[p];
    }

    // ---- compute-side lane addresses ----
    const int lane = tid & 31, wrp = tid >> 5;
    const int wm = wrp & 1, wn = wrp >> 1;
    const uint32_t as_base = (uint32_t)__cvta_generic_to_shared(&As[0][0][0]);
    const uint32_t bs_base = (uint32_t)__cvta_generic_to_shared(&Bs[0][0][0]);
    const uint32_t BUFB = BM * PADH * 2;   // 10240 bytes per buffer

    // A ldsm.x4 -> 4 matrices: (m0-7,k0-7),(m8-15,k0-7),(m0-7,k8-15),(m8-15,k8-15)
    const int arow_l = wm * 64 + (lane & 7) + 8 * ((lane >> 3) & 1);
    const int acol_b = 16 * (lane >> 4);                 // bytes
    const uint32_t aaddr0 = as_base + (uint32_t)(arow_l * (PADH * 2) + acol_b);
    // B ldsm.x4 -> (j0-7,k0-7),(j0-7,k8-15),(j8-15,k0-7),(j8-15,k8-15)
    const int brow_l = wn * 32 + (lane & 7) + 8 * (lane >> 4);
    const int bcol_b = 16 * ((lane >> 3) & 1);
    const uint32_t baddr0 = bs_base + (uint32_t)(brow_l * (PADH * 2) + bcol_b);

    float acc[4][4][4];
    #pragma unroll
    for (int mi = 0; mi < 4; mi++)
        #pragma unroll
        for (int nj = 0; nj < 4; nj++)
            #pragma unroll
            for (int q = 0; q < 4; q++) acc[mi][nj][q] = 0.f;

    const int KT = Kc / BK;
    float ra[2][4];
    float4 rb[2];

    // ---- prologue: stage tile 0 into buffer 0 ----
    #pragma unroll
    for (int p = 0; p < 2; p++) {
        if (A_COL) {
            #pragma unroll
            for (int j = 0; j < 4; j++)
                ra[p][j] = a_ptr[p][(size_t)j * M];
        } else {
            float4 v = *(const float4*)(a_ptr[p]);
            ra[p][0] = v.x; ra[p][1] = v.y; ra[p][2] = v.z; ra[p][3] = v.w;
        }
        rb[p] = b_ok[p] ? *(const float4*)(b_ptr[p])
                        : make_float4(0.f, 0.f, 0.f, 0.f);
    }
    #pragma unroll
    for (int p = 0; p < 2; p++) {
        uint2 va = make_uint2(f2h2(ra[p][0], ra[p][1]), f2h2(ra[p][2], ra[p][3]));
        *(uint2*)&As[0][a_m[p]][a_k[p]] = va;
        uint2 vb = make_uint2(f2h2(rb[p].x, rb[p].y), f2h2(rb[p].z, rb[p].w));
        *(uint2*)&Bs[0][b_j[p]][b_k[p]] = vb;
    }
    __syncthreads();

    int buf = 0;
    for (int kt = 0; kt < KT; kt++) {
        // prefetch next tile into registers (overlaps with MMA below)
        if (kt + 1 < KT) {
            #pragma unroll
            for (int p = 0; p < 2; p++) {
                if (A_COL) {
                    const float* ap = a_ptr[p] + (size_t)(kt + 1) * BK * M;
                    #pragma unroll
                    for (int j = 0; j < 4; j++)
                        ra[p][j] = ap[(size_t)j * M];
                } else {
                    float4 v = *(const float4*)(a_ptr[p] + (kt + 1) * BK);
                    ra[p][0] = v.x; ra[p][1] = v.y; ra[p][2] = v.z; ra[p][3] = v.w;
                }
                rb[p] = b_ok[p] ? *(const float4*)(b_ptr[p] + (kt + 1) * BK)
                                : make_float4(0.f, 0.f, 0.f, 0.f);
            }
        }

        // compute on current buffer
        const uint32_t abase = aaddr0 + buf * BUFB;
        const uint32_t bbase = baddr0 + buf * BUFB;
        uint32_t a[4][4], b[4][2];
        #pragma unroll
        for (int mi = 0; mi < 4; mi++)
            ldsm4(abase + (uint32_t)(mi * 16 * PADH * 2),
                  a[mi][0], a[mi][1], a[mi][2], a[mi][3]);
        #pragma unroll
        for (int njp = 0; njp < 2; njp++)
            ldsm4(bbase + (uint32_t)(njp * 16 * PADH * 2),
                  b[2 * njp][0], b[2 * njp][1], b[2 * njp + 1][0], b[2 * njp + 1][1]);
        #pragma unroll
        for (int mi = 0; mi < 4; mi++)
            #pragma unroll
            for (int nj = 0; nj < 4; nj++)
                mma16(acc[mi][nj], a[mi], b[nj]);

        // store prefetched tile into other buffer
        if (kt + 1 < KT) {
            int nb = buf ^ 1;
            #pragma unroll
            for (int p = 0; p < 2; p++) {
                uint2 va = make_uint2(f2h2(ra[p][0], ra[p][1]), f2h2(ra[p][2], ra[p][3]));
                *(uint2*)&As[nb][a_m[p]][a_k[p]] = va;
                uint2 vb = make_uint2(f2h2(rb[p].x, rb[p].y), f2h2(rb[p].z, rb[p].w));
                *(uint2*)&Bs[nb][b_j[p]][b_k[p]] = vb;
            }
        }
        __syncthreads();
        buf ^= 1;
    }

    // ---- epilogue (C layout of m16n8 same as tf32 path) ----
    const int r = lane >> 2, c = lane & 3;
    #pragma unroll
    for (int mi = 0; mi < 4; mi++) {
        int m = m0 + wm * 64 + mi * 16 + r;
        #pragma unroll
        for (int nj = 0; nj < 4; nj++) {
            int j = j0 + wn * 32 + nj * 8 + 2 * c;
            if (j < Nj) {
                float bj0 = HAS_BIAS ? bias[j]     : 0.f;
                float bj1 = HAS_BIAS ? bias[j + 1] : 0.f;
                float v0 = acc[mi][nj][0] + bj0;
                float v1 = acc[mi][nj][1] + bj1;
                float v2 = acc[mi][nj][2] + bj0;
                float v3 = acc[mi][nj][3] + bj1;
                if (OUT_T) {
                    out[(size_t)j * M + m]           = v0;
                    out[(size_t)(j + 1) * M + m]     = v1;
                    out[(size_t)j * M + m + 8]       = v2;
                    out[(size_t)(j + 1) * M + m + 8] = v3;
                } else {
                    *(float2*)&out[(size_t)m * Nj + j]       = make_float2(v0, v1);
                    *(float2*)&out[(size_t)(m + 8) * Nj + j] = make_float2(v2, v3);
                }
            }
        }
    }
}

// ---------------------------------------------------------------------------
// Depthwise 3x3 conv, SAME padding, float4: one thread = 4 consecutive x.
// ---------------------------------------------------------------------------
__global__ void __launch_bounds__(256)
dw_v4(const float* __restrict__ x, const float* __restrict__ w,
      const float* __restrict__ b, float* __restrict__ out)
{
    int t = blockIdx.x * blockDim.x + threadIdx.x;
    if (t >= NN * CC * HH * (WW / 4)) return;
    int x4 = (t & 15) * 4;
    int yy = (t >> 4) & (HH - 1);
    int c  = (t >> 10) & (CC - 1);
    int n  = t >> 18;

    const float* base = x + ((size_t)(n * CC + c) * HH) * WW;
    float wc[9];
    #pragma unroll
    for (int i = 0; i < 9; i++) wc[i] = w[c * 9 + i];

    float v[3][6];
    #pragma unroll
    for (int dy = 0; dy < 3; dy++) {
        int row = yy + dy - 1;
        if (row >= 0 && row < HH) {
            const float* rp = base + row * WW + x4;
            v[dy][0] = (x4 > 0) ? rp[-1] : 0.f;
            float4 m = *(const float4*)rp;
            v[dy][1] = m.x; v[dy][2] = m.y; v[dy][3] = m.z; v[dy][4] = m.w;
            v[dy][5] = (x4 + 4 < WW) ? rp[4] : 0.f;
        } else {
            #pragma unroll
            for (int i = 0; i < 6; i++) v[dy][i] = 0.f;
        }
    }

    float bc = b[c];
    float4 o;
    float* op = &o.x;
    #pragma unroll
    for (int i = 0; i < 4; i++) {
        float s = bc;
        #pragma unroll
        for (int dy = 0; dy < 3; dy++)
            #pragma unroll
            for (int dx = 0; dx < 3; dx++)
                s = fmaf(v[dy][i + dx], wc[dy * 3 + dx], s);
        op[i] = s;
    }
    *(float4*)(out + (size_t)((n * CC + c) * HH + yy) * WW + x4) = o;
}

// ---------------------------------------------------------------------------
// Deformable bilinear sampling, float4: one thread = (n, l, g, c4),
// 4 channels per thread. 8 lanes x 16B = one 128B transaction per corner.
// ---------------------------------------------------------------------------
__global__ void __launch_bounds__(256)
samp_v4(const float* __restrict__ value, const float* __restrict__ om,
        float* __restrict__ sampled)
{
    int t = blockIdx.x * blockDim.x + threadIdx.x;
    if (t >= NN * LL * GG * 8) return;
    int c4 = t & 7;
    int g  = (t >> 3) & (GG - 1);
    int nl = t >> 6;
    int l  = nl & (LL - 1);
    int n  = nl >> 12;
    int yy = l >> 6, xx = l & 63;

    const float* omp = om + nl * OMC + g * 27;
    const float* vb  = value + n * (LL * CC) + g * 32 + c4 * 4;

    float ax = 0.f, ay = 0.f, az = 0.f, aw = 0.f;
    #pragma unroll
    for (int k = 0; k < KK; k++) {
        float offy = omp[2 * k];
        float offx = omp[2 * k + 1];
        float msk  = omp[18 + k];
        float py = (float)(yy + k / 3 - 1) + offy;
        float px = (float)(xx + k % 3 - 1) + offx;
        float fy = floorf(py), fx = floorf(px);
        float tyf = py - fy, txf = px - fx;
        int y0 = (int)fy, x0 = (int)fx;

        bool yv0 = (unsigned)y0 < HH;
        bool yv1 = (unsigned)(y0 + 1) < HH;
        bool xv0 = (unsigned)x0 < WW;
        bool xv1 = (unsigned)(x0 + 1) < WW;

        float wy0 = 1.f - tyf, wx0 = 1.f - txf;
        float w00 = msk * wy0 * wx0;
        float w01 = msk * wy0 * txf;
        float w10 = msk * tyf * wx0;
        float w11 = msk * tyf * txf;

        const float* p = vb + (y0 * WW + x0) * CC;
        if (yv0 && xv0) {
            float4 v = *(const float4*)p;
            ax = fmaf(w00, v.x, ax); ay = fmaf(w00, v.y, ay);
            az = fmaf(w00, v.z, az); aw = fmaf(w00, v.w, aw);
        }
        if (yv0 && xv1) {
            float4 v = *(const float4*)(p + CC);
            ax = fmaf(w01, v.x, ax); ay = fmaf(w01, v.y, ay);
            az = fmaf(w01, v.z, az); aw = fmaf(w01, v.w, aw);
        }
        if (yv1 && xv0) {
            float4 v = *(const float4*)(p + WW * CC);
            ax = fmaf(w10, v.x, ax); ay = fmaf(w10, v.y, ay);
            az = fmaf(w10, v.z, az); aw = fmaf(w10, v.w, aw);
        }
        if (yv1 && xv1) {
            float4 v = *(const float4*)(p + WW * CC + CC);
            ax = fmaf(w11, v.x, ax); ay = fmaf(w11, v.y, ay);
            az = fmaf(w11, v.z, az); aw = fmaf(w11, v.w, aw);
        }
    }
    *(float4*)(sampled + nl * CC + g * 32 + c4 * 4) = make_float4(ax, ay, az, aw);
}

// ---------------------------------------------------------------------------
extern "C" void kernel_launch(void* const* d_in, const int* in_sizes, int n_in,
                              void* d_out, int out_size)
{
    const float* x   = (const float*)d_in[0];
    const float* dww = (const float*)d_in[1];
    const float* dwb = (const float*)d_in[2];
    const float* omw = (const float*)d_in[3];
    const float* omb = (const float*)d_in[4];
    const float* vpw = (const float*)d_in[5];
    const float* vpb = (const float*)d_in[6];
    const float* opw = (const float*)d_in[7];
    float* out = (float*)d_out;

    float *pval, *pomin, *pom, *psamp;
    cudaGetSymbolAddress((void**)&pval,  g_value);
    cudaGetSymbolAddress((void**)&pomin, g_omin);
    cudaGetSymbolAddress((void**)&pom,   g_om);
    cudaGetSymbolAddress((void**)&psamp, g_samp);

    // 1) value projection: (n,C,L) x -> value (n,L,C)
    gemm_hc<true, false, true><<<dim3(CC / 128, LL / 128, NN), 256>>>(
        x, vpw, vpb, pval, LL, CC, CC);

    // 2) depthwise conv -> om_in (n,C,L)
    dw_v4<<<(NN * CC * HH * (WW / 4) + 255) / 256, 256>>>(x, dww, dwb, pomin);

    // 3) offset/mask projection: om_in -> om (n,L,216)
    gemm_hc<true, false, true><<<dim3((OMC + 127) / 128, LL / 128, NN), 256>>>(
        pomin, omw, omb, pom, LL, OMC, CC);

    // 4) deformable sampling -> sampled (n,L,C)
    samp_v4<<<(NN * LL * GG * 8 + 255) / 256, 256>>>(pval, pom, psamp);

    // 5) output projection, write transposed directly to d_out (n,C,H,W)
    gemm_hc<false, true, false><<<dim3(CC / 128, LL / 128, NN), 256>>>(
        psamp, opw, nullptr, out, LL, CC, CC);
}

// round 8
// speedup vs baseline: 3.8727x; 1.1591x over previous
#include <cuda_runtime.h>
#include <cuda_fp16.h>
#include <cstdint>
#include <cstddef>

#define NN 8
#define CC 256
#define HH 64
#define WW 64
#define LL (HH*WW)      // 4096
#define GG 8
#define KK 9
#define OMC (GG*KK*3)   // 216

// Scratch (allocation-free: __device__ globals)
__device__ __half g_value[(size_t)NN*LL*CC];  // (n, L, C)  fp16
__device__ float  g_omin [(size_t)NN*CC*LL];  // (n, C, L)  depthwise output
__device__ float  g_om   [(size_t)NN*LL*OMC]; // (n, L, 216)
__device__ __half g_samp [(size_t)NN*LL*CC];  // (n, L, C)  fp16

// ---------------------------------------------------------------------------
// fp16 helpers
// ---------------------------------------------------------------------------
__device__ __forceinline__ uint32_t f2h2(float lo, float hi) {
    __half2 h = __floats2half2_rn(lo, hi);
    return *(uint32_t*)&h;
}
__device__ __forceinline__ void ldsm4(uint32_t addr, uint32_t& r0, uint32_t& r1,
                                      uint32_t& r2, uint32_t& r3) {
    asm volatile("ldmatrix.sync.aligned.m8n8.x4.shared.b16 {%0,%1,%2,%3}, [%4];"
                 : "=r"(r0), "=r"(r1), "=r"(r2), "=r"(r3) : "r"(addr));
}
__device__ __forceinline__ void mma16(float* d, const uint32_t* a, const uint32_t* b) {
    asm volatile("mma.sync.aligned.m16n8k16.row.col.f32.f16.f16.f32 "
                 "{%0,%1,%2,%3}, {%4,%5,%6,%7}, {%8,%9}, {%0,%1,%2,%3};"
                 : "+f"(d[0]), "+f"(d[1]), "+f"(d[2]), "+f"(d[3])
                 : "r"(a[0]), "r"(a[1]), "r"(a[2]), "r"(a[3]),
                   "r"(b[0]), "r"(b[1]));
}

// ---------------------------------------------------------------------------
// fp16 tensor-core batched GEMM (fp32 accumulate):
//   out[m][j] = sum_k a(m,k)*Wt[j*Kc+k] (+bias)
// TA (float/half): A element type. TO (float/half): out element type.
//   A_COL (TA=float only): a(m,k) = A[k*M + m], coalesced 4xLDG.32 along k
//   !A_COL: a(m,k) = A[m*Kc + k]
// BM=BN=128, BK=16, 256 threads. smem half, row stride 40 halves (80B):
// 16B-aligned rows, conflict-free ldmatrix/STS.
// ---------------------------------------------------------------------------
template<bool A_COL, bool OUT_T, bool HAS_BIAS, typename TA, typename TO>
__global__ void __launch_bounds__(256)
gemm_hc(const TA* __restrict__ A, const float* __restrict__ Wt,
        const float* __restrict__ bias, TO* __restrict__ out,
        int M, int Nj, int Kc)
{
    constexpr int BM = 128, BN = 128, BK = 16, PADH = 40;
    __shared__ __half As[2][BM][PADH];
    __shared__ __half Bs[2][BN][PADH];

    const int tid = threadIdx.x;
    const int bz = blockIdx.z;
    A   += (size_t)bz * M * Kc;
    out += (size_t)bz * M * Nj;
    const int m0 = blockIdx.y * BM;
    const int j0 = blockIdx.x * BN;

    // ---- staging setup: 2 chunks/thread/operand; chunk = (row, 4 k-values) --
    int a_m[2], a_k[2];
    const TA* a_ptr[2];
    int b_j[2], b_k[2];
    const float* b_ptr[2];
    bool b_ok[2];
    #pragma unroll
    for (int p = 0; p < 2; p++) {
        int q = tid + p * 256;
        if (A_COL) {
            a_m[p] = q & 127;
            a_k[p] = (q >> 7) * 4;
            a_ptr[p] = A + (size_t)a_k[p] * M + m0 + a_m[p];
        } else {
            int lin = q * 4;
            a_k[p] = lin & 15;  a_m[p] = lin >> 4;
            a_ptr[p] = A + (size_t)(m0 + a_m[p]) * Kc + a_k[p];
        }
        int lin = q * 4;
        b_k[p] = lin & 15; b_j[p] = lin >> 4;
        b_ok[p] = (j0 + b_j[p]) < Nj;
        b_ptr[p] = Wt + (size_t)(j0 + b_j[p]) * Kc + b_k[p];
    }

    const int lane = tid & 31, wrp = tid >> 5;
    const int wm = wrp & 1, wn = wrp >> 1;
    const uint32_t as_base = (uint32_t)__cvta_generic_to_shared(&As[0][0][0]);
    const uint32_t bs_base = (uint32_t)__cvta_generic_to_shared(&Bs[0][0][0]);
    const uint32_t BUFB = BM * PADH * 2;

    const int arow_l = wm * 64 + (lane & 7) + 8 * ((lane >> 3) & 1);
    const int acol_b = 16 * (lane >> 4);
    const uint32_t aaddr0 = as_base + (uint32_t)(arow_l * (PADH * 2) + acol_b);
    const int brow_l = wn * 32 + (lane & 7) + 8 * (lane >> 4);
    const int bcol_b = 16 * ((lane >> 3) & 1);
    const uint32_t baddr0 = bs_base + (uint32_t)(brow_l * (PADH * 2) + bcol_b);

    float acc[4][4][4];
    #pragma unroll
    for (int mi = 0; mi < 4; mi++)
        #pragma unroll
        for (int nj = 0; nj < 4; nj++)
            #pragma unroll
            for (int q = 0; q < 4; q++) acc[mi][nj][q] = 0.f;

    const int KT = Kc / BK;
    uint2 rah[2];       // staged A as 4 halves (half path)
    float raf[2][4];    // staged A as floats (float path)
    float4 rb[2];

    auto load_a = [&](int p, int kt) {
        if (sizeof(TA) == 2) {
            rah[p] = *(const uint2*)((const __half*)a_ptr[p] + kt * BK);
        } else if (A_COL) {
            const float* ap = (const float*)a_ptr[p] + (size_t)kt * BK * M;
            #pragma unroll
            for (int j = 0; j < 4; j++) raf[p][j] = ap[(size_t)j * M];
        } else {
            float4 v = *(const float4*)((const float*)a_ptr[p] + kt * BK);
            raf[p][0] = v.x; raf[p][1] = v.y; raf[p][2] = v.z; raf[p][3] = v.w;
        }
    };
    auto store_a = [&](int p, int nb) {
        uint2 va;
        if (sizeof(TA) == 2) va = rah[p];
        else va = make_uint2(f2h2(raf[p][0], raf[p][1]), f2h2(raf[p][2], raf[p][3]));
        *(uint2*)&As[nb][a_m[p]][a_k[p]] = va;
    };

    // ---- prologue ----
    #pragma unroll
    for (int p = 0; p < 2; p++) {
        load_a(p, 0);
        rb[p] = b_ok[p] ? *(const float4*)(b_ptr[p])
                        : make_float4(0.f, 0.f, 0.f, 0.f);
    }
    #pragma unroll
    for (int p = 0; p < 2; p++) {
        store_a(p, 0);
        uint2 vb = make_uint2(f2h2(rb[p].x, rb[p].y), f2h2(rb[p].z, rb[p].w));
        *(uint2*)&Bs[0][b_j[p]][b_k[p]] = vb;
    }
    __syncthreads();

    int buf = 0;
    for (int kt = 0; kt < KT; kt++) {
        if (kt + 1 < KT) {
            #pragma unroll
            for (int p = 0; p < 2; p++) {
                load_a(p, kt + 1);
                rb[p] = b_ok[p] ? *(const float4*)(b_ptr[p] + (kt + 1) * BK)
                                : make_float4(0.f, 0.f, 0.f, 0.f);
            }
        }

        const uint32_t abase = aaddr0 + buf * BUFB;
        const uint32_t bbase = baddr0 + buf * BUFB;
        uint32_t a[4][4], b[4][2];
        #pragma unroll
        for (int mi = 0; mi < 4; mi++)
            ldsm4(abase + (uint32_t)(mi * 16 * PADH * 2),
                  a[mi][0], a[mi][1], a[mi][2], a[mi][3]);
        #pragma unroll
        for (int njp = 0; njp < 2; njp++)
            ldsm4(bbase + (uint32_t)(njp * 16 * PADH * 2),
                  b[2 * njp][0], b[2 * njp][1], b[2 * njp + 1][0], b[2 * njp + 1][1]);
        #pragma unroll
        for (int mi = 0; mi < 4; mi++)
            #pragma unroll
            for (int nj = 0; nj < 4; nj++)
                mma16(acc[mi][nj], a[mi], b[nj]);

        if (kt + 1 < KT) {
            int nb = buf ^ 1;
            #pragma unroll
            for (int p = 0; p < 2; p++) {
                store_a(p, nb);
                uint2 vb = make_uint2(f2h2(rb[p].x, rb[p].y), f2h2(rb[p].z, rb[p].w));
                *(uint2*)&Bs[nb][b_j[p]][b_k[p]] = vb;
            }
        }
        __syncthreads();
        buf ^= 1;
    }

    // ---- epilogue ----
    const int r = lane >> 2, c = lane & 3;
    #pragma unroll
    for (int mi = 0; mi < 4; mi++) {
        int m = m0 + wm * 64 + mi * 16 + r;
        #pragma unroll
        for (int nj = 0; nj < 4; nj++) {
            int j = j0 + wn * 32 + nj * 8 + 2 * c;
            if (j < Nj) {
                float bj0 = HAS_BIAS ? bias[j]     : 0.f;
                float bj1 = HAS_BIAS ? bias[j + 1] : 0.f;
                float v0 = acc[mi][nj][0] + bj0;
                float v1 = acc[mi][nj][1] + bj1;
                float v2 = acc[mi][nj][2] + bj0;
                float v3 = acc[mi][nj][3] + bj1;
                if (OUT_T) {
                    // float output only (d_out)
                    ((float*)out)[(size_t)j * M + m]           = v0;
                    ((float*)out)[(size_t)(j + 1) * M + m]     = v1;
                    ((float*)out)[(size_t)j * M + m + 8]       = v2;
                    ((float*)out)[(size_t)(j + 1) * M + m + 8] = v3;
                } else if (sizeof(TO) == 2) {
                    *(uint32_t*)((__half*)out + (size_t)m * Nj + j)       = f2h2(v0, v1);
                    *(uint32_t*)((__half*)out + (size_t)(m + 8) * Nj + j) = f2h2(v2, v3);
                } else {
                    *(float2*)((float*)out + (size_t)m * Nj + j)       = make_float2(v0, v1);
                    *(float2*)((float*)out + (size_t)(m + 8) * Nj + j) = make_float2(v2, v3);
                }
            }
        }
    }
}

// ---------------------------------------------------------------------------
// Depthwise 3x3 conv, SAME padding, float4: one thread = 4 consecutive x.
// ---------------------------------------------------------------------------
__global__ void __launch_bounds__(256)
dw_v4(const float* __restrict__ x, const float* __restrict__ w,
      const float* __restrict__ b, float* __restrict__ out)
{
    int t = blockIdx.x * blockDim.x + threadIdx.x;
    if (t >= NN * CC * HH * (WW / 4)) return;
    int x4 = (t & 15) * 4;
    int yy = (t >> 4) & (HH - 1);
    int c  = (t >> 10) & (CC - 1);
    int n  = t >> 18;

    const float* base = x + ((size_t)(n * CC + c) * HH) * WW;
    float wc[9];
    #pragma unroll
    for (int i = 0; i < 9; i++) wc[i] = w[c * 9 + i];

    float v[3][6];
    #pragma unroll
    for (int dy = 0; dy < 3; dy++) {
        int row = yy + dy - 1;
        if (row >= 0 && row < HH) {
            const float* rp = base + row * WW + x4;
            v[dy][0] = (x4 > 0) ? rp[-1] : 0.f;
            float4 m = *(const float4*)rp;
            v[dy][1] = m.x; v[dy][2] = m.y; v[dy][3] = m.z; v[dy][4] = m.w;
            v[dy][5] = (x4 + 4 < WW) ? rp[4] : 0.f;
        } else {
            #pragma unroll
            for (int i = 0; i < 6; i++) v[dy][i] = 0.f;
        }
    }

    float bc = b[c];
    float4 o;
    float* op = &o.x;
    #pragma unroll
    for (int i = 0; i < 4; i++) {
        float s = bc;
        #pragma unroll
        for (int dy = 0; dy < 3; dy++)
            #pragma unroll
            for (int dx = 0; dx < 3; dx++)
                s = fmaf(v[dy][i + dx], wc[dy * 3 + dx], s);
        op[i] = s;
    }
    *(float4*)(out + (size_t)((n * CC + c) * HH + yy) * WW + x4) = o;
}

// ---------------------------------------------------------------------------
// Deformable bilinear sampling, fp16 value: one thread = (n, l, g, c8),
// 8 channels per thread (uint4 = 8 halves = 16B per corner load).
// One warp covers one (n,l) completely (8 g x 4 chunks).
// value:(n,L,C) half, om:(n,L,216) f32 -> sampled:(n,L,C) half
// ---------------------------------------------------------------------------
__global__ void __launch_bounds__(256)
samp_h8(const __half* __restrict__ value, const float* __restrict__ om,
        __half* __restrict__ sampled)
{
    int t = blockIdx.x * blockDim.x + threadIdx.x;
    if (t >= NN * LL * GG * 4) return;
    int c8 = (t & 3) * 8;           // channel chunk within group (32ch = 4 chunks)
    int g  = (t >> 2) & (GG - 1);
    int nl = t >> 5;                // n*L + l
    int l  = nl & (LL - 1);
    int n  = nl >> 12;
    int yy = l >> 6, xx = l & 63;

    const float*  omp = om + nl * OMC + g * 27;
    const __half* vb  = value + (size_t)n * (LL * CC) + g * 32 + c8;

    float a0 = 0.f, a1 = 0.f, a2 = 0.f, a3 = 0.f;
    float a4 = 0.f, a5 = 0.f, a6 = 0.f, a7 = 0.f;

    #pragma unroll
    for (int k = 0; k < KK; k++) {
        float offy = omp[2 * k];
        float offx = omp[2 * k + 1];
        float msk  = omp[18 + k];
        float py = (float)(yy + k / 3 - 1) + offy;
        float px = (float)(xx + k % 3 - 1) + offx;
        float fy = floorf(py), fx = floorf(px);
        float tyf = py - fy, txf = px - fx;
        int y0 = (int)fy, x0 = (int)fx;

        bool yv0 = (unsigned)y0 < HH;
        bool yv1 = (unsigned)(y0 + 1) < HH;
        bool xv0 = (unsigned)x0 < WW;
        bool xv1 = (unsigned)(x0 + 1) < WW;

        float wy0 = 1.f - tyf, wx0 = 1.f - txf;
        float w00 = msk * wy0 * wx0;
        float w01 = msk * wy0 * txf;
        float w10 = msk * tyf * wx0;
        float w11 = msk * tyf * txf;

        const __half* p = vb + (y0 * WW + x0) * CC;

        #pragma unroll
        for (int cr = 0; cr < 4; cr++) {
            bool ok; const __half* cp; float w;
            if (cr == 0)      { ok = yv0 && xv0; cp = p;                w = w00; }
            else if (cr == 1) { ok = yv0 && xv1; cp = p + CC;           w = w01; }
            else if (cr == 2) { ok = yv1 && xv0; cp = p + WW * CC;      w = w10; }
            else              { ok = yv1 && xv1; cp = p + WW * CC + CC; w = w11; }
            if (ok) {
                uint4 v = *(const uint4*)cp;
                float2 f0 = __half22float2(*(__half2*)&v.x);
                float2 f1 = __half22float2(*(__half2*)&v.y);
                float2 f2 = __half22float2(*(__half2*)&v.z);
                float2 f3 = __half22float2(*(__half2*)&v.w);
                a0 = fmaf(w, f0.x, a0); a1 = fmaf(w, f0.y, a1);
                a2 = fmaf(w, f1.x, a2); a3 = fmaf(w, f1.y, a3);
                a4 = fmaf(w, f2.x, a4); a5 = fmaf(w, f2.y, a5);
                a6 = fmaf(w, f3.x, a6); a7 = fmaf(w, f3.y, a7);
            }
        }
    }

    uint4 o;
    o.x = f2h2(a0, a1); o.y = f2h2(a2, a3);
    o.z = f2h2(a4, a5); o.w = f2h2(a6, a7);
    *(uint4*)(sampled + (size_t)nl * CC + g * 32 + c8) = o;
}

// ---------------------------------------------------------------------------
extern "C" void kernel_launch(void* const* d_in, const int* in_sizes, int n_in,
                              void* d_out, int out_size)
{
    const float* x   = (const float*)d_in[0];
    const float* dww = (const float*)d_in[1];
    const float* dwb = (const float*)d_in[2];
    const float* omw = (const float*)d_in[3];
    const float* omb = (const float*)d_in[4];
    const float* vpw = (const float*)d_in[5];
    const float* vpb = (const float*)d_in[6];
    const float* opw = (const float*)d_in[7];
    float* out = (float*)d_out;

    __half *pval, *psamp;
    float *pomin, *pom;
    cudaGetSymbolAddress((void**)&pval,  g_value);
    cudaGetSymbolAddress((void**)&pomin, g_omin);
    cudaGetSymbolAddress((void**)&pom,   g_om);
    cudaGetSymbolAddress((void**)&psamp, g_samp);

    // 1) value projection: (n,C,L) x -> value (n,L,C) fp16
    gemm_hc<true, false, true, float, __half>
        <<<dim3(CC / 128, LL / 128, NN), 256>>>(x, vpw, vpb, pval, LL, CC, CC);

    // 2) depthwise conv -> om_in (n,C,L)
    dw_v4<<<(NN * CC * HH * (WW / 4) + 255) / 256, 256>>>(x, dww, dwb, pomin);

    // 3) offset/mask projection: om_in -> om (n,L,216) fp32
    gemm_hc<true, false, true, float, float>
        <<<dim3((OMC + 127) / 128, LL / 128, NN), 256>>>(pomin, omw, omb, pom, LL, OMC, CC);

    // 4) deformable sampling -> sampled (n,L,C) fp16
    samp_h8<<<(NN * LL * GG * 4 + 255) / 256, 256>>>(pval, pom, psamp);

    // 5) output projection (half A), write transposed directly to d_out (n,C,H,W)
    gemm_hc<false, true, false, __half, float>
        <<<dim3(CC / 128, LL / 128, NN), 256>>>(psamp, opw, nullptr, out, LL, CC, CC);
}